// round 9
// baseline (speedup 1.0000x reference)
#include <cuda_runtime.h>
#include <cstdint>

// Problem constants
#define BB   2
#define TT   2048
#define DD   1024
#define HH   16
#define DHH  64
#define MM   (BB*TT)          // 4096
#define ATT_SCALE 0.125f      // DH^-0.5
#define LOG2E_F 1.4426950408889634f

// ---------------------------------------------------------------------------
// Scratch (allocation-free: __device__ globals)
// ---------------------------------------------------------------------------
__device__ __align__(256) float g_Q[BB*HH*TT*DHH];   // [b,h,t,dh] tf32-rounded
__device__ __align__(256) float g_K[BB*HH*TT*DHH];
__device__ __align__(256) float g_V[BB*HH*TT*DHH];
__device__ __align__(256) float g_O[MM*DD];          // [b,t,h*64+dh] tf32-rounded
__device__ __align__(256) float g_RIN[3*MM*DD];      // tf32-rounded query,key,value
__device__ __align__(256) float g_RW[4*DD*DD];       // tf32-rounded Wq,Wk,Wv,Wo
__device__ int   g_len[BB];

// ---------------------------------------------------------------------------
// Helpers
// ---------------------------------------------------------------------------
__device__ __forceinline__ uint32_t f2tf32(float x) {
    uint32_t r;
    asm("cvt.rna.tf32.f32 %0, %1;" : "=r"(r) : "f"(x));
    return r;
}
__device__ __forceinline__ float exp2_(float x) {
    float r;
    asm("ex2.approx.ftz.f32 %0, %1;" : "=f"(r) : "f"(x));
    return r;
}
__device__ __forceinline__ void mma16n8k8(float c[4], const uint32_t a[4], const uint32_t b[2]) {
    asm volatile("mma.sync.aligned.m16n8k8.row.col.f32.tf32.tf32.f32 "
        "{%0,%1,%2,%3}, {%4,%5,%6,%7}, {%8,%9}, {%0,%1,%2,%3};\n"
        : "+f"(c[0]), "+f"(c[1]), "+f"(c[2]), "+f"(c[3])
        : "r"(a[0]), "r"(a[1]), "r"(a[2]), "r"(a[3]), "r"(b[0]), "r"(b[1]));
}
__device__ __forceinline__ void cp16(void* s, const void* g) {
    uint32_t sa = (uint32_t)__cvta_generic_to_shared(s);
    asm volatile("cp.async.cg.shared.global [%0], [%1], 16;\n" :: "r"(sa), "l"(g));
}

// ---------------------------------------------------------------------------
// lens kernel (padding length per batch)
// ---------------------------------------------------------------------------
__global__ void lens_kernel(const unsigned char* __restrict__ kpm) {
    __shared__ int sred[256];
    const int b = blockIdx.x;
    const bool is_u8 = (kpm[TT - 1] != 0);
    int cnt = 0;
    if (is_u8) {
        const unsigned char* row = kpm + (size_t)b * TT;
        for (int t = threadIdx.x; t < TT; t += 256) cnt += (row[t] == 0);
    } else {
        const int* row = reinterpret_cast<const int*>(kpm) + (size_t)b * TT;
        for (int t = threadIdx.x; t < TT; t += 256) cnt += (row[t] == 0);
    }
    sred[threadIdx.x] = cnt;
    __syncthreads();
    for (int s = 128; s > 0; s >>= 1) {
        if (threadIdx.x < s) sred[threadIdx.x] += sred[threadIdx.x + s];
        __syncthreads();
    }
    if (threadIdx.x == 0) g_len[b] = sred[0];
}

// ---------------------------------------------------------------------------
// Pre-round inputs + weights to tf32 (RNA).
// ---------------------------------------------------------------------------
__global__ void __launch_bounds__(256) round_kernel(
    const float* __restrict__ q, const float* __restrict__ k, const float* __restrict__ v,
    const float* __restrict__ wq, const float* __restrict__ wk,
    const float* __restrict__ wv, const float* __restrict__ wo)
{
    const int y = blockIdx.y;
    const float* src; float* dst; int n4;
    if (y < 3) {
        src = (y == 0) ? q : (y == 1) ? k : v;
        dst = g_RIN + (size_t)y * (MM * DD);
        n4 = (MM * DD) / 4;
    } else {
        src = (y == 3) ? wq : (y == 4) ? wk : (y == 5) ? wv : wo;
        dst = g_RW + (size_t)(y - 3) * (DD * DD);
        n4 = (DD * DD) / 4;
    }
    const int i = blockIdx.x * 256 + threadIdx.x;
    if (i >= n4) return;
    float4 x = reinterpret_cast<const float4*>(src)[i];
    x.x = __uint_as_float(f2tf32(x.x));
    x.y = __uint_as_float(f2tf32(x.y));
    x.z = __uint_as_float(f2tf32(x.z));
    x.w = __uint_as_float(f2tf32(x.w));
    reinterpret_cast<float4*>(dst)[i] = x;
}

// ---------------------------------------------------------------------------
// TF32 mma.sync GEMM v3: 128-thread CTAs (2 CTAs/SM), 128x128 tile, BK=32,
// 2x2 warps of 64x64, explicit ks-level fragment double-buffering.
// ---------------------------------------------------------------------------
#define PBM 128
#define PBN 128
#define PBK 32
#define PPD 36
#define PNKT (DD / PBK)
#define PASZ (PBM * PPD)
#define PBSZ (PBN * PPD)
#define PSMEM (2 * (PASZ + PBSZ) * 4)   // 73,728 B

template<bool ROUND_OUT, bool HEAD_MAJOR>
__device__ __forceinline__ void gemm_body(const float* __restrict__ A,
                                          const float* __restrict__ W,
                                          float* __restrict__ out)
{
    extern __shared__ float sm[];
    float* As = sm;                 // [2][128][36]
    float* Bs = sm + 2 * PASZ;      // [2][128][36]

    const int tid  = threadIdx.x;
    const int lane = tid & 31, warp = tid >> 5;
    const int wm = warp >> 1, wn = warp & 1;        // 2x2 warp grid
    const int bm = blockIdx.y * PBM, bn = blockIdx.x * PBN;
    const int lq = lane >> 2, lr = lane & 3;

    float acc[4][8][4];
#pragma unroll
    for (int mt = 0; mt < 4; mt++)
#pragma unroll
        for (int nt = 0; nt < 8; nt++)
#pragma unroll
            for (int j = 0; j < 4; j++) acc[mt][nt][j] = 0.f;

    const float* Abase = A + (size_t)bm * DD;
    const float* Wbase = W + (size_t)bn * DD;

    // stage loader: 128 rows x 8 float4 chunks per matrix, 128 threads -> 8 each
    auto load_tile = [&](int kt, int buf) {
        const int k0 = kt * PBK;
#pragma unroll
        for (int i = 0; i < 8; i++) {
            const int idx = tid + i * 128;
            const int r = idx >> 3, j = idx & 7;
            cp16(&As[buf * PASZ + r * PPD + j * 4], Abase + (size_t)r * DD + k0 + j * 4);
        }
#pragma unroll
        for (int i = 0; i < 8; i++) {
            const int idx = tid + i * 128;
            const int r = idx >> 3, j = idx & 7;
            cp16(&Bs[buf * PBSZ + r * PPD + j * 4], Wbase + (size_t)r * DD + k0 + j * 4);
        }
        asm volatile("cp.async.commit_group;\n");
    };

    load_tile(0, 0);

    uint32_t af[2][4][4], bf[2][8][2];

    for (int kt = 0; kt < PNKT; kt++) {
        const int buf = kt & 1;
        if (kt + 1 < PNKT) {
            load_tile(kt + 1, buf ^ 1);
            asm volatile("cp.async.wait_group 1;\n");
        } else {
            asm volatile("cp.async.wait_group 0;\n");
        }
        __syncthreads();

        const float* Ab = &As[buf * PASZ];
        const float* Bb = &Bs[buf * PBSZ];

        // prefetch ks=0 fragments
        {
            const int c = lr;
#pragma unroll
            for (int mt = 0; mt < 4; mt++) {
                const int r = wm * 64 + mt * 16 + lq;
                af[0][mt][0] = __float_as_uint(Ab[r * PPD + c]);
                af[0][mt][1] = __float_as_uint(Ab[(r + 8) * PPD + c]);
                af[0][mt][2] = __float_as_uint(Ab[r * PPD + c + 4]);
                af[0][mt][3] = __float_as_uint(Ab[(r + 8) * PPD + c + 4]);
            }
#pragma unroll
            for (int nt = 0; nt < 8; nt++) {
                const int n = wn * 64 + nt * 8 + lq;
                bf[0][nt][0] = __float_as_uint(Bb[n * PPD + c]);
                bf[0][nt][1] = __float_as_uint(Bb[n * PPD + c + 4]);
            }
        }

#pragma unroll
        for (int ks = 0; ks < 4; ks++) {
            const int cur = ks & 1;
            if (ks < 3) {
                const int c = (ks + 1) * 8 + lr;
                const int nxt = cur ^ 1;
#pragma unroll
                for (int mt = 0; mt < 4; mt++) {
                    const int r = wm * 64 + mt * 16 + lq;
                    af[nxt][mt][0] = __float_as_uint(Ab[r * PPD + c]);
                    af[nxt][mt][1] = __float_as_uint(Ab[(r + 8) * PPD + c]);
                    af[nxt][mt][2] = __float_as_uint(Ab[r * PPD + c + 4]);
                    af[nxt][mt][3] = __float_as_uint(Ab[(r + 8) * PPD + c + 4]);
                }
#pragma unroll
                for (int nt = 0; nt < 8; nt++) {
                    const int n = wn * 64 + nt * 8 + lq;
                    bf[nxt][nt][0] = __float_as_uint(Bb[n * PPD + c]);
                    bf[nxt][nt][1] = __float_as_uint(Bb[n * PPD + c + 4]);
                }
            }
#pragma unroll
            for (int nt = 0; nt < 8; nt++)
#pragma unroll
                for (int mt = 0; mt < 4; mt++)
                    mma16n8k8(acc[mt][nt], af[cur][mt], bf[cur][nt]);
        }
        __syncthreads();
    }

    // epilogue
#pragma unroll
    for (int mt = 0; mt < 4; mt++) {
        const int gm = bm + wm * 64 + mt * 16 + lq;
#pragma unroll
        for (int nt = 0; nt < 8; nt++) {
            const int gn = bn + wn * 64 + nt * 8 + (lr << 1);
            float v0 = acc[mt][nt][0], v1 = acc[mt][nt][1];
            float v2 = acc[mt][nt][2], v3 = acc[mt][nt][3];
            if (ROUND_OUT) {
                v0 = __uint_as_float(f2tf32(v0)); v1 = __uint_as_float(f2tf32(v1));
                v2 = __uint_as_float(f2tf32(v2)); v3 = __uint_as_float(f2tf32(v3));
            }
            if (HEAD_MAJOR) {
                const int h = gn >> 6, dh = gn & 63;
                const int b0 = gm >> 11, t0 = gm & (TT - 1);
                *reinterpret_cast<float2*>(
                    &out[(((size_t)b0 * HH + h) * TT + t0) * DHH + dh]) = make_float2(v0, v1);
                const int gm1 = gm + 8;
                const int b1 = gm1 >> 11, t1 = gm1 & (TT - 1);
                *reinterpret_cast<float2*>(
                    &out[(((size_t)b1 * HH + h) * TT + t1) * DHH + dh]) = make_float2(v2, v3);
            } else {
                *reinterpret_cast<float2*>(&out[(size_t)gm * DD + gn]) = make_float2(v0, v1);
                *reinterpret_cast<float2*>(&out[(size_t)(gm + 8) * DD + gn]) = make_float2(v2, v3);
            }
        }
    }
}

__global__ void __launch_bounds__(128, 2)
proj_qkv_kernel()
{
    const int z = blockIdx.z;
    const float* A = g_RIN + (size_t)z * (MM * DD);
    const float* W = g_RW + (size_t)z * (DD * DD);
    float* out = (z == 0) ? g_Q : (z == 1) ? g_K : g_V;
    gemm_body<true, true>(A, W, out);
}

__global__ void __launch_bounds__(128, 2)
proj_o_kernel(float* __restrict__ out)
{
    gemm_body<false, false>(g_O, g_RW + 3 * (size_t)(DD * DD), out);
}

// ---------------------------------------------------------------------------
// Flash attention: 128 q-rows/CTA, 4 warps x 32 rows, double-buffered KV,
// warp-private P buffer, reversed-qi launch + dead warp-tile skipping.
// ---------------------------------------------------------------------------
#define AKP 68
#define AVP 72
#define A_KS_OFF 0
#define A_VS_OFF 8704
#define A_PS_OFF 17920
#define A_SMEM   ((17920 + 8704) * 4)   // 106,496 B

__global__ void __launch_bounds__(128, 2) attn_kernel()
{
    extern __shared__ float sm[];
    float* Ps = sm + A_PS_OFF;

    const int qi = gridDim.x - 1 - blockIdx.x;   // heavy CTAs first
    const int h = blockIdx.y, b = blockIdx.z;
    const int tid = threadIdx.x, warp = tid >> 5, lane = tid & 31;
    const int len = g_len[b];
    const int lq = lane >> 2, lr = lane & 3;

    const size_t base = ((size_t)b * HH + h) * TT * DHH;
    const float* __restrict__ Qb = g_Q + base;
    const float* __restrict__ Kb = g_K + base;
    const float* __restrict__ Vb = g_V + base;

    // ---- stage Q tile coalesced into Ps, then fragments ----
#pragma unroll
    for (int i = 0; i < 16; i++) {
        const int idx = tid + i * 128;
        const int r = idx >> 4, c4 = (idx & 15) << 2;
        *reinterpret_cast<float4*>(&Ps[r * AKP + c4]) =
            *reinterpret_cast<const float4*>(&Qb[(size_t)(qi * 128 + r) * DHH + c4]);
    }
    __syncthreads();

    uint32_t qf[2][8][4];
    {
        const int r0 = warp * 32 + lq;
#pragma unroll
        for (int mt = 0; mt < 2; mt++) {
            const int rA = r0 + mt * 16;
#pragma unroll
            for (int ks = 0; ks < 8; ks++) {
                const int c = ks * 8 + lr;
                qf[mt][ks][0] = __float_as_uint(Ps[rA * AKP + c]);
                qf[mt][ks][1] = __float_as_uint(Ps[(rA + 8) * AKP + c]);
                qf[mt][ks][2] = __float_as_uint(Ps[rA * AKP + c + 4]);
                qf[mt][ks][3] = __float_as_uint(Ps[(rA + 8) * AKP + c + 4]);
            }
        }
    }
    __syncthreads();

    float oacc[2][8][4];
#pragma unroll
    for (int mt = 0; mt < 2; mt++)
#pragma unroll
        for (int nt = 0; nt < 8; nt++)
#pragma unroll
            for (int j = 0; j < 4; j++) oacc[mt][nt][j] = 0.f;

    float mrow[2][2], lrow[2][2];
#pragma unroll
    for (int mt = 0; mt < 2; mt++) {
        mrow[mt][0] = -1e30f; mrow[mt][1] = -1e30f;
        lrow[mt][0] = 0.f;    lrow[mt][1] = 0.f;
    }

    const int ktend = min(2 * qi + 2, (len + 63) >> 6);
    const float SE = ATT_SCALE * LOG2E_F;
    const int warp_row_end = qi * 128 + warp * 32 + 32;   // exclusive

    auto load_kv = [&](int kt, int bufi) {
        const float* Kp = Kb + (size_t)(kt * 64) * DHH;
        const float* Vp = Vb + (size_t)(kt * 64) * DHH;
        float* Kd = sm + A_KS_OFF + bufi * 64 * AKP;
        float* Vd = sm + A_VS_OFF + bufi * 64 * AVP;
#pragma unroll
        for (int i = 0; i < 8; i++) {
            const int idx = tid + i * 128;
            const int r = idx >> 4, c4 = (idx & 15) << 2;
            cp16(Kd + r * AKP + c4, Kp + (size_t)r * DHH + c4);
            cp16(Vd + r * AVP + c4, Vp + (size_t)r * DHH + c4);
        }
        asm volatile("cp.async.commit_group;\n");
    };

    load_kv(0, 0);

    const int prow = warp * 32 + lq;

    for (int kt = 0; kt < ktend; kt++) {
        const int buf = kt & 1;
        asm volatile("cp.async.wait_group 0;\n");
        __syncthreads();
        if (kt + 1 < ktend) load_kv(kt + 1, buf ^ 1);

        // skip warp tiles that are fully causally masked
        if (kt * 64 >= warp_row_end) continue;

        const float* Kt = sm + A_KS_OFF + buf * 64 * AKP;
        const float* Vt = sm + A_VS_OFF + buf * 64 * AVP;

        // ---- S = Q K^T ----
        float s[2][8][4];
#pragma unroll
        for (int mt = 0; mt < 2; mt++)
#pragma unroll
            for (int nt = 0; nt < 8; nt++)
#pragma unroll
                for (int j = 0; j < 4; j++) s[mt][nt][j] = 0.f;
#pragma unroll
        for (int ks = 0; ks < 8; ks++) {
            const int c = ks * 8 + lr;
#pragma unroll
            for (int nt = 0; nt < 8; nt++) {
                const int n = nt * 8 + lq;
                uint32_t bfr[2];
                bfr[0] = __float_as_uint(Kt[n * AKP + c]);
                bfr[1] = __float_as_uint(Kt[n * AKP + c + 4]);
                mma16n8k8(s[0][nt], qf[0][ks], bfr);
                mma16n8k8(s[1][nt], qf[1][ks], bfr);
            }
        }

        // ---- scale + mask ----
        const bool need_mask = (kt >= 2 * qi) || (((kt + 1) << 6) > len);
#pragma unroll
        for (int mt = 0; mt < 2; mt++) {
            const int qg0 = qi * 128 + warp * 32 + mt * 16 + lq;
#pragma unroll
            for (int nt = 0; nt < 8; nt++) {
#pragma unroll
                for (int j = 0; j < 4; j++) {
                    float v = s[mt][nt][j] * SE;
                    if (need_mask) {
                        const int kg = kt * 64 + nt * 8 + (lr << 1) + (j & 1);
                        const int qg = qg0 + ((j & 2) << 2);
                        if (kg > qg || kg >= len) v = -1e30f;
                    }
                    s[mt][nt][j] = v;
                }
            }
        }

        // ---- softmax + P store + O rescale ----
#pragma unroll
        for (int mt = 0; mt < 2; mt++) {
            float tA = -1e30f, tB = -1e30f;
#pragma unroll
            for (int nt = 0; nt < 8; nt++) {
                tA = fmaxf(tA, fmaxf(s[mt][nt][0], s[mt][nt][1]));
                tB = fmaxf(tB, fmaxf(s[mt][nt][2], s[mt][nt][3]));
            }
            tA = fmaxf(tA, __shfl_xor_sync(0xffffffffu, tA, 1));
            tA = fmaxf(tA, __shfl_xor_sync(0xffffffffu, tA, 2));
            tB = fmaxf(tB, __shfl_xor_sync(0xffffffffu, tB, 1));
            tB = fmaxf(tB, __shfl_xor_sync(0xffffffffu, tB, 2));
            const float mA = fmaxf(mrow[mt][0], tA), mB = fmaxf(mrow[mt][1], tB);
            const float aA = exp2_(mrow[mt][0] - mA), aB = exp2_(mrow[mt][1] - mB);

            float rA = 0.f, rB = 0.f;
            const int pr = prow + mt * 16;
#pragma unroll
            for (int nt = 0; nt < 8; nt++) {
                const float p0 = exp2_(s[mt][nt][0] - mA);
                const float p1 = exp2_(s[mt][nt][1] - mA);
                const float p2 = exp2_(s[mt][nt][2] - mB);
                const float p3 = exp2_(s[mt][nt][3] - mB);
                rA += p0 + p1;
                rB += p2 + p3;
                const int c = nt * 8 + (lr << 1);
                *reinterpret_cast<float2*>(&Ps[pr * AKP + c]) = make_float2(
                    __uint_as_float(f2tf32(p0)), __uint_as_float(f2tf32(p1)));
                *reinterpret_cast<float2*>(&Ps[(pr + 8) * AKP + c]) = make_float2(
                    __uint_as_float(f2tf32(p2)), __uint_as_float(f2tf32(p3)));
            }
            rA += __shfl_xor_sync(0xffffffffu, rA, 1);
            rA += __shfl_xor_sync(0xffffffffu, rA, 2);
            rB += __shfl_xor_sync(0xffffffffu, rB, 1);
            rB += __shfl_xor_sync(0xffffffffu, rB, 2);
            lrow[mt][0] = lrow[mt][0] * aA + rA;
            lrow[mt][1] = lrow[mt][1] * aB + rB;
            mrow[mt][0] = mA;
            mrow[mt][1] = mB;
#pragma unroll
            for (int nt = 0; nt < 8; nt++) {
                oacc[mt][nt][0] *= aA; oacc[mt][nt][1] *= aA;
                oacc[mt][nt][2] *= aB; oacc[mt][nt][3] *= aB;
            }
        }
        __syncwarp();

        // ---- O += P V ----
#pragma unroll
        for (int ks = 0; ks < 8; ks++) {
            uint32_t pa[2][4];
            const int c = ks * 8 + lr;
#pragma unroll
            for (int mt = 0; mt < 2; mt++) {
                const int pr = prow + mt * 16;
                pa[mt][0] = __float_as_uint(Ps[pr * AKP + c]);
                pa[mt][1] = __float_as_uint(Ps[(pr + 8) * AKP + c]);
                pa[mt][2] = __float_as_uint(Ps[pr * AKP + c + 4]);
                pa[mt][3] = __float_as_uint(Ps[(pr + 8) * AKP + c + 4]);
            }
#pragma unroll
            for (int nt = 0; nt < 8; nt++) {
                const int n = nt * 8 + lq;
                uint32_t bfr[2];
                bfr[0] = __float_as_uint(Vt[(ks * 8 + lr) * AVP + n]);
                bfr[1] = __float_as_uint(Vt[(ks * 8 + lr + 4) * AVP + n]);
                mma16n8k8(oacc[0][nt], pa[0], bfr);
                mma16n8k8(oacc[1][nt], pa[1], bfr);
            }
        }
        __syncwarp();
    }

    // ---- finalize (tf32-rounded for the O projection) ----
    float* __restrict__ Ob = g_O + ((size_t)b * TT) * DD + h * DHH;
#pragma unroll
    for (int mt = 0; mt < 2; mt++) {
        const float invA = 1.f / lrow[mt][0], invB = 1.f / lrow[mt][1];
        const int q0 = qi * 128 + warp * 32 + mt * 16 + lq;
#pragma unroll
        for (int nt = 0; nt < 8; nt++) {
            const int dh = nt * 8 + (lr << 1);
            *reinterpret_cast<float2*>(&Ob[(size_t)q0 * DD + dh]) = make_float2(
                __uint_as_float(f2tf32(oacc[mt][nt][0] * invA)),
                __uint_as_float(f2tf32(oacc[mt][nt][1] * invA)));
            *reinterpret_cast<float2*>(&Ob[(size_t)(q0 + 8) * DD + dh]) = make_float2(
                __uint_as_float(f2tf32(oacc[mt][nt][2] * invB)),
                __uint_as_float(f2tf32(oacc[mt][nt][3] * invB)));
        }
    }
}

// ---------------------------------------------------------------------------
// Launch
// ---------------------------------------------------------------------------
extern "C" void kernel_launch(void* const* d_in, const int* in_sizes, int n_in,
                              void* d_out, int out_size)
{
    const float* big[4] = {nullptr, nullptr, nullptr, nullptr};
    const float* w[4]   = {nullptr, nullptr, nullptr, nullptr};
    const unsigned char* kpm = nullptr;
    int nbig = 0, nw = 0;
    for (int i = 0; i < n_in; i++) {
        if (in_sizes[i] == TT * TT && nbig < 4) big[nbig++] = (const float*)d_in[i];
        else if (in_sizes[i] == DD * DD && nw < 4) w[nw++] = (const float*)d_in[i];
        else if (in_sizes[i] == BB * TT) kpm = (const unsigned char*)d_in[i];
    }
    const float* query = big[0];
    const float* key_t = big[1];
    const float* value = big[2];
    const float* Wq = w[0];
    const float* Wk = w[1];
    const float* Wv = w[2];
    const float* Wo = w[3];
    float* out = (float*)d_out;

    static bool attr_set = false;
    if (!attr_set) {
        cudaFuncSetAttribute(proj_qkv_kernel, cudaFuncAttributeMaxDynamicSharedMemorySize, PSMEM);
        cudaFuncSetAttribute(proj_o_kernel, cudaFuncAttributeMaxDynamicSharedMemorySize, PSMEM);
        cudaFuncSetAttribute(attn_kernel, cudaFuncAttributeMaxDynamicSharedMemorySize, A_SMEM);
        attr_set = true;
    }

    lens_kernel<<<BB, 256>>>(kpm);
    round_kernel<<<dim3((MM * DD) / 4 / 256, 7), 256>>>(query, key_t, value, Wq, Wk, Wv, Wo);
    proj_qkv_kernel<<<dim3(DD / PBN, MM / PBM, 3), 128, PSMEM>>>();
    attn_kernel<<<dim3(TT / 128, HH, BB), 128, A_SMEM>>>();
    proj_o_kernel<<<dim3(DD / PBN, MM / PBM, 1), 128, PSMEM>>>(out);
}

// round 10
// speedup vs baseline: 1.6707x; 1.6707x over previous
#include <cuda_runtime.h>
#include <cuda_fp16.h>
#include <cstdint>

// Problem constants
#define BB   2
#define TT   2048
#define DD   1024
#define HH   16
#define DHH  64
#define MM   (BB*TT)          // 4096
#define ATT_SCALE 0.125f      // DH^-0.5
#define LOG2E_F 1.4426950408889634f

// ---------------------------------------------------------------------------
// Scratch (allocation-free: __device__ globals), all fp16 now
// ---------------------------------------------------------------------------
__device__ __align__(256) __half g_Q[BB*HH*TT*DHH];   // [b,h,t,dh]
__device__ __align__(256) __half g_K[BB*HH*TT*DHH];
__device__ __align__(256) __half g_V[BB*HH*TT*DHH];
__device__ __align__(256) __half g_O[MM*DD];          // [b,t,h*64+dh]
__device__ __align__(256) __half g_RIN[3*MM*DD];      // fp16 query,key,value
__device__ __align__(256) __half g_RW[4*DD*DD];       // fp16 Wq,Wk,Wv,Wo
__device__ int   g_len[BB];

// ---------------------------------------------------------------------------
// Helpers
// ---------------------------------------------------------------------------
__device__ __forceinline__ float exp2_(float x) {
    float r;
    asm("ex2.approx.ftz.f32 %0, %1;" : "=f"(r) : "f"(x));
    return r;
}
__device__ __forceinline__ uint32_t packh2(float a, float b) {
    __half2 h = __floats2half2_rn(a, b);
    return *reinterpret_cast<uint32_t*>(&h);
}
// fp16 MMA, fp32 accumulate: D = A(16x16) * B(16x8) + D
__device__ __forceinline__ void mma16n8k16(float c[4], const uint32_t a[4], const uint32_t b[2]) {
    asm volatile("mma.sync.aligned.m16n8k16.row.col.f32.f16.f16.f32 "
        "{%0,%1,%2,%3}, {%4,%5,%6,%7}, {%8,%9}, {%0,%1,%2,%3};\n"
        : "+f"(c[0]), "+f"(c[1]), "+f"(c[2]), "+f"(c[3])
        : "r"(a[0]), "r"(a[1]), "r"(a[2]), "r"(a[3]), "r"(b[0]), "r"(b[1]));
}
__device__ __forceinline__ void cp16(void* s, const void* g) {
    uint32_t sa = (uint32_t)__cvta_generic_to_shared(s);
    asm volatile("cp.async.cg.shared.global [%0], [%1], 16;\n" :: "r"(sa), "l"(g));
}
__device__ __forceinline__ uint32_t lds32(const __half* p) {
    return *reinterpret_cast<const uint32_t*>(p);
}

// ---------------------------------------------------------------------------
// lens kernel (padding length per batch)
// ---------------------------------------------------------------------------
__global__ void lens_kernel(const unsigned char* __restrict__ kpm) {
    __shared__ int sred[256];
    const int b = blockIdx.x;
    const bool is_u8 = (kpm[TT - 1] != 0);
    int cnt = 0;
    if (is_u8) {
        const unsigned char* row = kpm + (size_t)b * TT;
        for (int t = threadIdx.x; t < TT; t += 256) cnt += (row[t] == 0);
    } else {
        const int* row = reinterpret_cast<const int*>(kpm) + (size_t)b * TT;
        for (int t = threadIdx.x; t < TT; t += 256) cnt += (row[t] == 0);
    }
    sred[threadIdx.x] = cnt;
    __syncthreads();
    for (int s = 128; s > 0; s >>= 1) {
        if (threadIdx.x < s) sred[threadIdx.x] += sred[threadIdx.x + s];
        __syncthreads();
    }
    if (threadIdx.x == 0) g_len[b] = sred[0];
}

// ---------------------------------------------------------------------------
// Convert inputs + weights to fp16 (RN).
// ---------------------------------------------------------------------------
__global__ void __launch_bounds__(256) round_kernel(
    const float* __restrict__ q, const float* __restrict__ k, const float* __restrict__ v,
    const float* __restrict__ wq, const float* __restrict__ wk,
    const float* __restrict__ wv, const float* __restrict__ wo)
{
    const int y = blockIdx.y;
    const float* src; __half* dst; int n4;
    if (y < 3) {
        src = (y == 0) ? q : (y == 1) ? k : v;
        dst = g_RIN + (size_t)y * (MM * DD);
        n4 = (MM * DD) / 4;
    } else {
        src = (y == 3) ? wq : (y == 4) ? wk : (y == 5) ? wv : wo;
        dst = g_RW + (size_t)(y - 3) * (DD * DD);
        n4 = (DD * DD) / 4;
    }
    const int i = blockIdx.x * 256 + threadIdx.x;
    if (i >= n4) return;
    float4 x = reinterpret_cast<const float4*>(src)[i];
    uint2 o;
    o.x = packh2(x.x, x.y);
    o.y = packh2(x.z, x.w);
    reinterpret_cast<uint2*>(dst)[i] = o;
}

// ---------------------------------------------------------------------------
// FP16 mma.sync GEMM: 128-thread CTAs, 128x128 tile, BK=32 (2 k16 steps),
// 2x2 warps of 64x64, double-buffered smem + ks-level fragment double-buffer.
// out[m,n] = sum_k A[m,k]*W[n,k]
// ---------------------------------------------------------------------------
#define PBM 128
#define PBN 128
#define PBK 32
#define PPDH 40                      // half pitch: 32 data + 8 pad
#define PNKT (DD / PBK)              // 32
#define PASZH (PBM * PPDH)           // 5120 halves per buffer
#define PSMEM (4 * PASZH * 2)        // 40,960 B

// MODE 0: fp16 out, head-major [b,h,t,dh]. MODE 1: fp32 out, row-major [M,N].
template<int MODE>
__device__ __forceinline__ void gemm_body(const __half* __restrict__ A,
                                          const __half* __restrict__ W,
                                          void* __restrict__ outp)
{
    extern __shared__ __half smh[];
    __half* As = smh;                 // [2][128][40]
    __half* Bs = smh + 2 * PASZH;     // [2][128][40]

    const int tid  = threadIdx.x;
    const int lane = tid & 31, warp = tid >> 5;
    const int wm = warp >> 1, wn = warp & 1;
    const int bm = blockIdx.y * PBM, bn = blockIdx.x * PBN;
    const int lq = lane >> 2, lr = lane & 3;

    float acc[4][8][4];
#pragma unroll
    for (int mt = 0; mt < 4; mt++)
#pragma unroll
        for (int nt = 0; nt < 8; nt++)
#pragma unroll
            for (int j = 0; j < 4; j++) acc[mt][nt][j] = 0.f;

    const __half* Abase = A + (size_t)bm * DD;
    const __half* Wbase = W + (size_t)bn * DD;

    // stage: 128 rows x 4 chunks (16B = 8 halves) per matrix
    auto load_tile = [&](int kt, int buf) {
        const int k0 = kt * PBK;
#pragma unroll
        for (int i = 0; i < 4; i++) {
            const int idx = tid + i * 128;
            const int r = idx >> 2, j = idx & 3;
            cp16(&As[buf * PASZH + r * PPDH + j * 8], Abase + (size_t)r * DD + k0 + j * 8);
        }
#pragma unroll
        for (int i = 0; i < 4; i++) {
            const int idx = tid + i * 128;
            const int r = idx >> 2, j = idx & 3;
            cp16(&Bs[buf * PASZH + r * PPDH + j * 8], Wbase + (size_t)r * DD + k0 + j * 8);
        }
        asm volatile("cp.async.commit_group;\n");
    };

    load_tile(0, 0);

    uint32_t af[2][4][4], bf[2][8][2];

    for (int kt = 0; kt < PNKT; kt++) {
        const int buf = kt & 1;
        if (kt + 1 < PNKT) {
            load_tile(kt + 1, buf ^ 1);
            asm volatile("cp.async.wait_group 1;\n");
        } else {
            asm volatile("cp.async.wait_group 0;\n");
        }
        __syncthreads();

        const __half* Ab = &As[buf * PASZH];
        const __half* Bb = &Bs[buf * PASZH];

        // prefetch ks=0 fragments
        {
            const int c = 2 * lr;
#pragma unroll
            for (int mt = 0; mt < 4; mt++) {
                const int r = wm * 64 + mt * 16 + lq;
                af[0][mt][0] = lds32(&Ab[r * PPDH + c]);
                af[0][mt][1] = lds32(&Ab[(r + 8) * PPDH + c]);
                af[0][mt][2] = lds32(&Ab[r * PPDH + c + 8]);
                af[0][mt][3] = lds32(&Ab[(r + 8) * PPDH + c + 8]);
            }
#pragma unroll
            for (int nt = 0; nt < 8; nt++) {
                const int n = wn * 64 + nt * 8 + lq;
                bf[0][nt][0] = lds32(&Bb[n * PPDH + c]);
                bf[0][nt][1] = lds32(&Bb[n * PPDH + c + 8]);
            }
        }

#pragma unroll
        for (int ks = 0; ks < 2; ks++) {
            const int cur = ks & 1;
            if (ks < 1) {
                const int c = 16 + 2 * lr;
                const int nxt = cur ^ 1;
#pragma unroll
                for (int mt = 0; mt < 4; mt++) {
                    const int r = wm * 64 + mt * 16 + lq;
                    af[nxt][mt][0] = lds32(&Ab[r * PPDH + c]);
                    af[nxt][mt][1] = lds32(&Ab[(r + 8) * PPDH + c]);
                    af[nxt][mt][2] = lds32(&Ab[r * PPDH + c + 8]);
                    af[nxt][mt][3] = lds32(&Ab[(r + 8) * PPDH + c + 8]);
                }
#pragma unroll
                for (int nt = 0; nt < 8; nt++) {
                    const int n = wn * 64 + nt * 8 + lq;
                    bf[nxt][nt][0] = lds32(&Bb[n * PPDH + c]);
                    bf[nxt][nt][1] = lds32(&Bb[n * PPDH + c + 8]);
                }
            }
#pragma unroll
            for (int nt = 0; nt < 8; nt++)
#pragma unroll
                for (int mt = 0; mt < 4; mt++)
                    mma16n8k16(acc[mt][nt], af[cur][mt], bf[cur][nt]);
        }
        __syncthreads();
    }

    // epilogue
#pragma unroll
    for (int mt = 0; mt < 4; mt++) {
        const int gm = bm + wm * 64 + mt * 16 + lq;
#pragma unroll
        for (int nt = 0; nt < 8; nt++) {
            const int gn = bn + wn * 64 + nt * 8 + (lr << 1);
            if (MODE == 0) {
                __half* out = (__half*)outp;
                const int h = gn >> 6, dh = gn & 63;
                const int b0 = gm >> 11, t0 = gm & (TT - 1);
                *reinterpret_cast<uint32_t*>(
                    &out[(((size_t)b0 * HH + h) * TT + t0) * DHH + dh]) =
                    packh2(acc[mt][nt][0], acc[mt][nt][1]);
                const int gm1 = gm + 8;
                const int b1 = gm1 >> 11, t1 = gm1 & (TT - 1);
                *reinterpret_cast<uint32_t*>(
                    &out[(((size_t)b1 * HH + h) * TT + t1) * DHH + dh]) =
                    packh2(acc[mt][nt][2], acc[mt][nt][3]);
            } else {
                float* out = (float*)outp;
                *reinterpret_cast<float2*>(&out[(size_t)gm * DD + gn]) =
                    make_float2(acc[mt][nt][0], acc[mt][nt][1]);
                *reinterpret_cast<float2*>(&out[(size_t)(gm + 8) * DD + gn]) =
                    make_float2(acc[mt][nt][2], acc[mt][nt][3]);
            }
        }
    }
}

__global__ void __launch_bounds__(128, 2)
proj_qkv_kernel()
{
    const int z = blockIdx.z;
    const __half* A = g_RIN + (size_t)z * (MM * DD);
    const __half* W = g_RW + (size_t)z * (DD * DD);
    __half* out = (z == 0) ? g_Q : (z == 1) ? g_K : g_V;
    gemm_body<0>(A, W, out);
}

__global__ void __launch_bounds__(128, 2)
proj_o_kernel(float* __restrict__ out)
{
    gemm_body<1>(g_O, g_RW + 3 * (size_t)(DD * DD), out);
}

// ---------------------------------------------------------------------------
// FP16 flash attention: 128 q-rows/CTA, 4 warps x 32 rows, 64-key tiles
// double-buffered, warp-private fp16 P buffer, ldmatrix.trans for V.
// ---------------------------------------------------------------------------
#define AKPH 72                          // half pitch for all attn tiles
#define A_KS_OFF 0                       // Ks[2][64][72]  = 9216 halves
#define A_VS_OFF 9216                    // Vs[2][64][72]  = 9216 halves
#define A_PS_OFF 18432                   // Ps[128][72]    = 9216 halves
#define A_SMEM   ((18432 + 9216) * 2)    // 55,296 B

__global__ void __launch_bounds__(128, 2) attn_kernel()
{
    extern __shared__ __half smh[];
    __half* Ps = smh + A_PS_OFF;

    const int qi = blockIdx.x, h = blockIdx.y, b = blockIdx.z;
    const int tid = threadIdx.x, warp = tid >> 5, lane = tid & 31;
    const int len = g_len[b];
    const int lq = lane >> 2, lr = lane & 3;

    const size_t base = ((size_t)b * HH + h) * TT * DHH;
    const __half* __restrict__ Qb = g_Q + base;
    const __half* __restrict__ Kb = g_K + base;
    const __half* __restrict__ Vb = g_V + base;

    // ---- stage Q tile (128 x 64 halves) into Ps, coalesced ----
#pragma unroll
    for (int i = 0; i < 8; i++) {
        const int idx = tid + i * 128;
        const int r = idx >> 3, j = idx & 7;     // 8 chunks of 8 halves per row
        *reinterpret_cast<uint4*>(&Ps[r * AKPH + j * 8]) =
            *reinterpret_cast<const uint4*>(&Qb[(size_t)(qi * 128 + r) * DHH + j * 8]);
    }
    __syncthreads();

    // Q fragments: 2 m-tiles x 4 k16 steps x 4 regs
    uint32_t qf[2][4][4];
    {
        const int r0 = warp * 32 + lq;
#pragma unroll
        for (int mt = 0; mt < 2; mt++) {
            const int rA = r0 + mt * 16;
#pragma unroll
            for (int ks = 0; ks < 4; ks++) {
                const int c = ks * 16 + 2 * lr;
                qf[mt][ks][0] = lds32(&Ps[rA * AKPH + c]);
                qf[mt][ks][1] = lds32(&Ps[(rA + 8) * AKPH + c]);
                qf[mt][ks][2] = lds32(&Ps[rA * AKPH + c + 8]);
                qf[mt][ks][3] = lds32(&Ps[(rA + 8) * AKPH + c + 8]);
            }
        }
    }
    __syncthreads();   // Ps free for P use

    float oacc[2][8][4];
#pragma unroll
    for (int mt = 0; mt < 2; mt++)
#pragma unroll
        for (int nt = 0; nt < 8; nt++)
#pragma unroll
            for (int j = 0; j < 4; j++) oacc[mt][nt][j] = 0.f;

    float mrow[2][2], lrow[2][2];
#pragma unroll
    for (int mt = 0; mt < 2; mt++) {
        mrow[mt][0] = -1e30f; mrow[mt][1] = -1e30f;
        lrow[mt][0] = 0.f;    lrow[mt][1] = 0.f;
    }

    const int ktend = min(2 * qi + 2, (len + 63) >> 6);
    const float SE = ATT_SCALE * LOG2E_F;
    const int warp_row_end = qi * 128 + warp * 32 + 32;

    auto load_kv = [&](int kt, int bufi) {
        const __half* Kp = Kb + (size_t)(kt * 64) * DHH;
        const __half* Vp = Vb + (size_t)(kt * 64) * DHH;
        __half* Kd = smh + A_KS_OFF + bufi * 64 * AKPH;
        __half* Vd = smh + A_VS_OFF + bufi * 64 * AKPH;
#pragma unroll
        for (int i = 0; i < 4; i++) {
            const int idx = tid + i * 128;
            const int r = idx >> 3, j = idx & 7;
            cp16(Kd + r * AKPH + j * 8, Kp + (size_t)r * DHH + j * 8);
            cp16(Vd + r * AKPH + j * 8, Vp + (size_t)r * DHH + j * 8);
        }
        asm volatile("cp.async.commit_group;\n");
    };

    load_kv(0, 0);

    const int prow = warp * 32 + lq;

    for (int kt = 0; kt < ktend; kt++) {
        const int buf = kt & 1;
        asm volatile("cp.async.wait_group 0;\n");
        __syncthreads();
        if (kt + 1 < ktend) load_kv(kt + 1, buf ^ 1);

        if (kt * 64 >= warp_row_end) continue;   // fully causally masked warp tile

        const __half* Kt = smh + A_KS_OFF + buf * 64 * AKPH;
        const __half* Vt = smh + A_VS_OFF + buf * 64 * AKPH;

        // ---- S = Q K^T ----
        float s[2][8][4];
#pragma unroll
        for (int mt = 0; mt < 2; mt++)
#pragma unroll
            for (int nt = 0; nt < 8; nt++)
#pragma unroll
                for (int j = 0; j < 4; j++) s[mt][nt][j] = 0.f;
#pragma unroll
        for (int ks = 0; ks < 4; ks++) {
            const int c = ks * 16 + 2 * lr;
#pragma unroll
            for (int nt = 0; nt < 8; nt++) {
                const int n = nt * 8 + lq;
                uint32_t bfr[2];
                bfr[0] = lds32(&Kt[n * AKPH + c]);
                bfr[1] = lds32(&Kt[n * AKPH + c + 8]);
                mma16n8k16(s[0][nt], qf[0][ks], bfr);
                mma16n8k16(s[1][nt], qf[1][ks], bfr);
            }
        }

        // ---- scale + mask ----
        const bool need_mask = (kt >= 2 * qi) || (((kt + 1) << 6) > len);
#pragma unroll
        for (int mt = 0; mt < 2; mt++) {
            const int qg0 = qi * 128 + warp * 32 + mt * 16 + lq;
#pragma unroll
            for (int nt = 0; nt < 8; nt++) {
#pragma unroll
                for (int j = 0; j < 4; j++) {
                    float v = s[mt][nt][j] * SE;
                    if (need_mask) {
                        const int kg = kt * 64 + nt * 8 + (lr << 1) + (j & 1);
                        const int qg = qg0 + ((j & 2) << 2);
                        if (kg > qg || kg >= len) v = -1e30f;
                    }
                    s[mt][nt][j] = v;
                }
            }
        }

        // ---- softmax + fp16 P store + O rescale ----
#pragma unroll
        for (int mt = 0; mt < 2; mt++) {
            float tA = -1e30f, tB = -1e30f;
#pragma unroll
            for (int nt = 0; nt < 8; nt++) {
                tA = fmaxf(tA, fmaxf(s[mt][nt][0], s[mt][nt][1]));
                tB = fmaxf(tB, fmaxf(s[mt][nt][2], s[mt][nt][3]));
            }
            tA = fmaxf(tA, __shfl_xor_sync(0xffffffffu, tA, 1));
            tA = fmaxf(tA, __shfl_xor_sync(0xffffffffu, tA, 2));
            tB = fmaxf(tB, __shfl_xor_sync(0xffffffffu, tB, 1));
            tB = fmaxf(tB, __shfl_xor_sync(0xffffffffu, tB, 2));
            const float mA = fmaxf(mrow[mt][0], tA), mB = fmaxf(mrow[mt][1], tB);
            const float aA = exp2_(mrow[mt][0] - mA), aB = exp2_(mrow[mt][1] - mB);

            float rA = 0.f, rB = 0.f;
            const int pr = prow + mt * 16;
#pragma unroll
            for (int nt = 0; nt < 8; nt++) {
                const float p0 = exp2_(s[mt][nt][0] - mA);
                const float p1 = exp2_(s[mt][nt][1] - mA);
                const float p2 = exp2_(s[mt][nt][2] - mB);
                const float p3 = exp2_(s[mt][nt][3] - mB);
                rA += p0 + p1;
                rB += p2 + p3;
                const int c = nt * 8 + (lr << 1);
                *reinterpret_cast<uint32_t*>(&Ps[pr * AKPH + c]) = packh2(p0, p1);
                *reinterpret_cast<uint32_t*>(&Ps[(pr + 8) * AKPH + c]) = packh2(p2, p3);
            }
            rA += __shfl_xor_sync(0xffffffffu, rA, 1);
            rA += __shfl_xor_sync(0xffffffffu, rA, 2);
            rB += __shfl_xor_sync(0xffffffffu, rB, 1);
            rB += __shfl_xor_sync(0xffffffffu, rB, 2);
            lrow[mt][0] = lrow[mt][0] * aA + rA;
            lrow[mt][1] = lrow[mt][1] * aB + rB;
            mrow[mt][0] = mA;
            mrow[mt][1] = mB;
#pragma unroll
            for (int nt = 0; nt < 8; nt++) {
                oacc[mt][nt][0] *= aA; oacc[mt][nt][1] *= aA;
                oacc[mt][nt][2] *= aB; oacc[mt][nt][3] *= aB;
            }
        }
        __syncwarp();

        // ---- O += P V  (V B-frags via ldmatrix.x4.trans) ----
        const uint32_t vt_u32 = (uint32_t)__cvta_generic_to_shared(Vt);
#pragma unroll
        for (int ks = 0; ks < 4; ks++) {
            uint32_t pa[2][4];
            const int c = ks * 16 + 2 * lr;
#pragma unroll
            for (int mt = 0; mt < 2; mt++) {
                const int pr = prow + mt * 16;
                pa[mt][0] = lds32(&Ps[pr * AKPH + c]);
                pa[mt][1] = lds32(&Ps[(pr + 8) * AKPH + c]);
                pa[mt][2] = lds32(&Ps[pr * AKPH + c + 8]);
                pa[mt][3] = lds32(&Ps[(pr + 8) * AKPH + c + 8]);
            }
#pragma unroll
            for (int ntp = 0; ntp < 4; ntp++) {
                const int row = ks * 16 + ((lane >> 3) & 1) * 8 + (lane & 7);
                const int col = ntp * 16 + ((lane >> 4) << 3);
                const uint32_t addr = vt_u32 + (uint32_t)(row * AKPH + col) * 2;
                uint32_t v0, v1, v2, v3;
                asm volatile("ldmatrix.sync.aligned.m8n8.x4.trans.shared.b16 "
                    "{%0,%1,%2,%3}, [%4];"
                    : "=r"(v0), "=r"(v1), "=r"(v2), "=r"(v3) : "r"(addr));
                uint32_t b0[2] = {v0, v1}, b1[2] = {v2, v3};
                mma16n8k16(oacc[0][2 * ntp],     pa[0], b0);
                mma16n8k16(oacc[1][2 * ntp],     pa[1], b0);
                mma16n8k16(oacc[0][2 * ntp + 1], pa[0], b1);
                mma16n8k16(oacc[1][2 * ntp + 1], pa[1], b1);
            }
        }
        __syncwarp();
    }

    // ---- finalize: fp16 O in [b,t,h*64+dh] ----
    __half* __restrict__ Ob = g_O + ((size_t)b * TT) * DD + h * DHH;
#pragma unroll
    for (int mt = 0; mt < 2; mt++) {
        const float invA = 1.f / lrow[mt][0], invB = 1.f / lrow[mt][1];
        const int q0 = qi * 128 + warp * 32 + mt * 16 + lq;
#pragma unroll
        for (int nt = 0; nt < 8; nt++) {
            const int dh = nt * 8 + (lr << 1);
            *reinterpret_cast<uint32_t*>(&Ob[(size_t)q0 * DD + dh]) =
                packh2(oacc[mt][nt][0] * invA, oacc[mt][nt][1] * invA);
            *reinterpret_cast<uint32_t*>(&Ob[(size_t)(q0 + 8) * DD + dh]) =
                packh2(oacc[mt][nt][2] * invB, oacc[mt][nt][3] * invB);
        }
    }
}

// ---------------------------------------------------------------------------
// Launch
// ---------------------------------------------------------------------------
extern "C" void kernel_launch(void* const* d_in, const int* in_sizes, int n_in,
                              void* d_out, int out_size)
{
    const float* big[4] = {nullptr, nullptr, nullptr, nullptr};
    const float* w[4]   = {nullptr, nullptr, nullptr, nullptr};
    const unsigned char* kpm = nullptr;
    int nbig = 0, nw = 0;
    for (int i = 0; i < n_in; i++) {
        if (in_sizes[i] == TT * TT && nbig < 4) big[nbig++] = (const float*)d_in[i];
        else if (in_sizes[i] == DD * DD && nw < 4) w[nw++] = (const float*)d_in[i];
        else if (in_sizes[i] == BB * TT) kpm = (const unsigned char*)d_in[i];
    }
    const float* query = big[0];
    const float* key_t = big[1];
    const float* value = big[2];
    const float* Wq = w[0];
    const float* Wk = w[1];
    const float* Wv = w[2];
    const float* Wo = w[3];
    float* out = (float*)d_out;

    static bool attr_set = false;
    if (!attr_set) {
        cudaFuncSetAttribute(proj_qkv_kernel, cudaFuncAttributeMaxDynamicSharedMemorySize, PSMEM);
        cudaFuncSetAttribute(proj_o_kernel, cudaFuncAttributeMaxDynamicSharedMemorySize, PSMEM);
        cudaFuncSetAttribute(attn_kernel, cudaFuncAttributeMaxDynamicSharedMemorySize, A_SMEM);
        attr_set = true;
    }

    lens_kernel<<<BB, 256>>>(kpm);
    round_kernel<<<dim3((MM * DD) / 4 / 256, 7), 256>>>(query, key_t, value, Wq, Wk, Wv, Wo);
    proj_qkv_kernel<<<dim3(DD / PBN, MM / PBM, 3), 128, PSMEM>>>();
    attn_kernel<<<dim3(TT / 128, HH, BB), 128, A_SMEM>>>();
    proj_o_kernel<<<dim3(DD / PBN, MM / PBM, 1), 128, PSMEM>>>(out);
}

// round 11
// speedup vs baseline: 1.7920x; 1.0726x over previous
#include <cuda_runtime.h>
#include <cuda_fp16.h>
#include <cstdint>

// Problem constants
#define BB   2
#define TT   2048
#define DD   1024
#define HH   16
#define DHH  64
#define MM   (BB*TT)          // 4096
#define ATT_SCALE 0.125f      // DH^-0.5
#define LOG2E_F 1.4426950408889634f

// ---------------------------------------------------------------------------
// Scratch (allocation-free: __device__ globals), all fp16
// ---------------------------------------------------------------------------
__device__ __align__(256) __half g_Q[BB*HH*TT*DHH];   // [b,h,t,dh]
__device__ __align__(256) __half g_K[BB*HH*TT*DHH];
__device__ __align__(256) __half g_V[BB*HH*TT*DHH];
__device__ __align__(256) __half g_O[MM*DD];          // [b,t,h*64+dh]
__device__ __align__(256) __half g_RIN[3*MM*DD];      // fp16 query,key,value
__device__ __align__(256) __half g_RW[4*DD*DD];       // fp16 Wq,Wk,Wv,Wo
__device__ int   g_len[BB];

// ---------------------------------------------------------------------------
// Helpers
// ---------------------------------------------------------------------------
__device__ __forceinline__ float exp2_(float x) {
    float r;
    asm("ex2.approx.ftz.f32 %0, %1;" : "=f"(r) : "f"(x));
    return r;
}
__device__ __forceinline__ uint32_t packh2(float a, float b) {
    __half2 h = __floats2half2_rn(a, b);
    return *reinterpret_cast<uint32_t*>(&h);
}
__device__ __forceinline__ void mma16n8k16(float c[4], const uint32_t a[4], const uint32_t b[2]) {
    asm volatile("mma.sync.aligned.m16n8k16.row.col.f32.f16.f16.f32 "
        "{%0,%1,%2,%3}, {%4,%5,%6,%7}, {%8,%9}, {%0,%1,%2,%3};\n"
        : "+f"(c[0]), "+f"(c[1]), "+f"(c[2]), "+f"(c[3])
        : "r"(a[0]), "r"(a[1]), "r"(a[2]), "r"(a[3]), "r"(b[0]), "r"(b[1]));
}
__device__ __forceinline__ void cp16(void* s, const void* g) {
    uint32_t sa = (uint32_t)__cvta_generic_to_shared(s);
    asm volatile("cp.async.cg.shared.global [%0], [%1], 16;\n" :: "r"(sa), "l"(g));
}
__device__ __forceinline__ void ldsm4(uint32_t addr, uint32_t r[4]) {
    asm volatile("ldmatrix.sync.aligned.m8n8.x4.shared.b16 {%0,%1,%2,%3}, [%4];"
        : "=r"(r[0]), "=r"(r[1]), "=r"(r[2]), "=r"(r[3]) : "r"(addr));
}
__device__ __forceinline__ void ldsm4t(uint32_t addr, uint32_t r[4]) {
    asm volatile("ldmatrix.sync.aligned.m8n8.x4.trans.shared.b16 {%0,%1,%2,%3}, [%4];"
        : "=r"(r[0]), "=r"(r[1]), "=r"(r[2]), "=r"(r[3]) : "r"(addr));
}

// ---------------------------------------------------------------------------
// lens kernel (padding length per batch)
// ---------------------------------------------------------------------------
__global__ void lens_kernel(const unsigned char* __restrict__ kpm) {
    __shared__ int sred[256];
    const int b = blockIdx.x;
    const bool is_u8 = (kpm[TT - 1] != 0);
    int cnt = 0;
    if (is_u8) {
        const unsigned char* row = kpm + (size_t)b * TT;
        for (int t = threadIdx.x; t < TT; t += 256) cnt += (row[t] == 0);
    } else {
        const int* row = reinterpret_cast<const int*>(kpm) + (size_t)b * TT;
        for (int t = threadIdx.x; t < TT; t += 256) cnt += (row[t] == 0);
    }
    sred[threadIdx.x] = cnt;
    __syncthreads();
    for (int s = 128; s > 0; s >>= 1) {
        if (threadIdx.x < s) sred[threadIdx.x] += sred[threadIdx.x + s];
        __syncthreads();
    }
    if (threadIdx.x == 0) g_len[b] = sred[0];
}

// ---------------------------------------------------------------------------
// Convert inputs + weights to fp16 (RN).
// ---------------------------------------------------------------------------
__global__ void __launch_bounds__(256) round_kernel(
    const float* __restrict__ q, const float* __restrict__ k, const float* __restrict__ v,
    const float* __restrict__ wq, const float* __restrict__ wk,
    const float* __restrict__ wv, const float* __restrict__ wo)
{
    const int y = blockIdx.y;
    const float* src; __half* dst; int n4;
    if (y < 3) {
        src = (y == 0) ? q : (y == 1) ? k : v;
        dst = g_RIN + (size_t)y * (MM * DD);
        n4 = (MM * DD) / 4;
    } else {
        src = (y == 3) ? wq : (y == 4) ? wk : (y == 5) ? wv : wo;
        dst = g_RW + (size_t)(y - 3) * (DD * DD);
        n4 = (DD * DD) / 4;
    }
    const int i = blockIdx.x * 256 + threadIdx.x;
    if (i >= n4) return;
    float4 x = reinterpret_cast<const float4*>(src)[i];
    uint2 o;
    o.x = packh2(x.x, x.y);
    o.y = packh2(x.z, x.w);
    reinterpret_cast<uint2*>(dst)[i] = o;
}

// ---------------------------------------------------------------------------
// FP16 mma.sync GEMM with LDSM operand loads: 128-thread CTAs, 128x128 tile,
// BK=32 (2 k16 steps), 2x2 warps of 64x64.
// ---------------------------------------------------------------------------
#define PBM 128
#define PBN 128
#define PBK 32
#define PPDH 40                      // half pitch: 32 data + 8 pad (80 B)
#define PNKT (DD / PBK)              // 32
#define PASZH (PBM * PPDH)           // 5120 halves per buffer
#define PSMEM (4 * PASZH * 2)        // 40,960 B

template<int MODE>   // 0: fp16 head-major out; 1: fp32 row-major out
__device__ __forceinline__ void gemm_body(const __half* __restrict__ A,
                                          const __half* __restrict__ W,
                                          void* __restrict__ outp)
{
    extern __shared__ __half smh[];
    __half* As = smh;                 // [2][128][40]
    __half* Bs = smh + 2 * PASZH;     // [2][128][40]

    const int tid  = threadIdx.x;
    const int lane = tid & 31, warp = tid >> 5;
    const int wm = warp >> 1, wn = warp & 1;
    const int bm = blockIdx.y * PBM, bn = blockIdx.x * PBN;
    const int lq = lane >> 2, lr = lane & 3;
    const int sub = lane >> 3, l7 = lane & 7;

    float acc[4][8][4];
#pragma unroll
    for (int mt = 0; mt < 4; mt++)
#pragma unroll
        for (int nt = 0; nt < 8; nt++)
#pragma unroll
            for (int j = 0; j < 4; j++) acc[mt][nt][j] = 0.f;

    const __half* Abase = A + (size_t)bm * DD;
    const __half* Wbase = W + (size_t)bn * DD;

    auto load_tile = [&](int kt, int buf) {
        const int k0 = kt * PBK;
#pragma unroll
        for (int i = 0; i < 4; i++) {
            const int idx = tid + i * 128;
            const int r = idx >> 2, j = idx & 3;
            cp16(&As[buf * PASZH + r * PPDH + j * 8], Abase + (size_t)r * DD + k0 + j * 8);
        }
#pragma unroll
        for (int i = 0; i < 4; i++) {
            const int idx = tid + i * 128;
            const int r = idx >> 2, j = idx & 3;
            cp16(&Bs[buf * PASZH + r * PPDH + j * 8], Wbase + (size_t)r * DD + k0 + j * 8);
        }
        asm volatile("cp.async.commit_group;\n");
    };

    load_tile(0, 0);

    for (int kt = 0; kt < PNKT; kt++) {
        const int buf = kt & 1;
        if (kt + 1 < PNKT) {
            load_tile(kt + 1, buf ^ 1);
            asm volatile("cp.async.wait_group 1;\n");
        } else {
            asm volatile("cp.async.wait_group 0;\n");
        }
        __syncthreads();

        const uint32_t Abu = (uint32_t)__cvta_generic_to_shared(&As[buf * PASZH]);
        const uint32_t Bbu = (uint32_t)__cvta_generic_to_shared(&Bs[buf * PASZH]);

#pragma unroll
        for (int ks = 0; ks < 2; ks++) {
            const int c = ks * 16;
            uint32_t af[4][4], bfq[4][4];
            // A frags: x4 = (m0-7,k0-7),(m8-15,k0-7),(m0-7,k8-15),(m8-15,k8-15)
            {
                const int row_off = (sub & 1) * 8 + l7;
                const int col = c + (sub >> 1) * 8;
#pragma unroll
                for (int mt = 0; mt < 4; mt++) {
                    const int row = wm * 64 + mt * 16 + row_off;
                    ldsm4(Abu + (uint32_t)(row * PPDH + col) * 2, af[mt]);
                }
            }
            // B frags: x4 = (n0-7,k0-7),(n0-7,k8-15),(n8-15,k0-7),(n8-15,k8-15)
            {
                const int row_off = (sub >> 1) * 8 + l7;
                const int col = c + (sub & 1) * 8;
#pragma unroll
                for (int ntp = 0; ntp < 4; ntp++) {
                    const int row = wn * 64 + ntp * 16 + row_off;
                    ldsm4(Bbu + (uint32_t)(row * PPDH + col) * 2, bfq[ntp]);
                }
            }
#pragma unroll
            for (int ntp = 0; ntp < 4; ntp++) {
                uint32_t b0[2] = {bfq[ntp][0], bfq[ntp][1]};
                uint32_t b1[2] = {bfq[ntp][2], bfq[ntp][3]};
#pragma unroll
                for (int mt = 0; mt < 4; mt++) {
                    mma16n8k16(acc[mt][2 * ntp],     af[mt], b0);
                    mma16n8k16(acc[mt][2 * ntp + 1], af[mt], b1);
                }
            }
        }
        __syncthreads();
    }

    // epilogue
#pragma unroll
    for (int mt = 0; mt < 4; mt++) {
        const int gm = bm + wm * 64 + mt * 16 + lq;
#pragma unroll
        for (int nt = 0; nt < 8; nt++) {
            const int gn = bn + wn * 64 + nt * 8 + (lr << 1);
            if (MODE == 0) {
                __half* out = (__half*)outp;
                const int h = gn >> 6, dh = gn & 63;
                const int b0 = gm >> 11, t0 = gm & (TT - 1);
                *reinterpret_cast<uint32_t*>(
                    &out[(((size_t)b0 * HH + h) * TT + t0) * DHH + dh]) =
                    packh2(acc[mt][nt][0], acc[mt][nt][1]);
                const int gm1 = gm + 8;
                const int b1 = gm1 >> 11, t1 = gm1 & (TT - 1);
                *reinterpret_cast<uint32_t*>(
                    &out[(((size_t)b1 * HH + h) * TT + t1) * DHH + dh]) =
                    packh2(acc[mt][nt][2], acc[mt][nt][3]);
            } else {
                float* out = (float*)outp;
                *reinterpret_cast<float2*>(&out[(size_t)gm * DD + gn]) =
                    make_float2(acc[mt][nt][0], acc[mt][nt][1]);
                *reinterpret_cast<float2*>(&out[(size_t)(gm + 8) * DD + gn]) =
                    make_float2(acc[mt][nt][2], acc[mt][nt][3]);
            }
        }
    }
}

__global__ void __launch_bounds__(128, 2)
proj_qkv_kernel()
{
    const int z = blockIdx.z;
    const __half* A = g_RIN + (size_t)z * (MM * DD);
    const __half* W = g_RW + (size_t)z * (DD * DD);
    __half* out = (z == 0) ? g_Q : (z == 1) ? g_K : g_V;
    gemm_body<0>(A, W, out);
}

__global__ void __launch_bounds__(128, 2)
proj_o_kernel(float* __restrict__ out)
{
    gemm_body<1>(g_O, g_RW + 3 * (size_t)(DD * DD), out);
}

// ---------------------------------------------------------------------------
// FP16 flash attention with LDSM operand loads.
// ---------------------------------------------------------------------------
#define AKPH 72                          // half pitch (144 B)
#define A_KS_OFF 0
#define A_VS_OFF 9216
#define A_PS_OFF 18432
#define A_SMEM   ((18432 + 9216) * 2)    // 55,296 B

__global__ void __launch_bounds__(128, 2) attn_kernel()
{
    extern __shared__ __half smh[];
    __half* Ps = smh + A_PS_OFF;

    const int qi = blockIdx.x, h = blockIdx.y, b = blockIdx.z;
    const int tid = threadIdx.x, warp = tid >> 5, lane = tid & 31;
    const int len = g_len[b];
    const int lq = lane >> 2, lr = lane & 3;
    const int sub = lane >> 3, l7 = lane & 7;

    const size_t base = ((size_t)b * HH + h) * TT * DHH;
    const __half* __restrict__ Qb = g_Q + base;
    const __half* __restrict__ Kb = g_K + base;
    const __half* __restrict__ Vb = g_V + base;

    const uint32_t ps_u = (uint32_t)__cvta_generic_to_shared(Ps);

    // ---- stage Q tile, then LDSM fragments ----
#pragma unroll
    for (int i = 0; i < 8; i++) {
        const int idx = tid + i * 128;
        const int r = idx >> 3, j = idx & 7;
        *reinterpret_cast<uint4*>(&Ps[r * AKPH + j * 8]) =
            *reinterpret_cast<const uint4*>(&Qb[(size_t)(qi * 128 + r) * DHH + j * 8]);
    }
    __syncthreads();

    uint32_t qf[2][4][4];
    {
        const int row_off = (sub & 1) * 8 + l7;
        const int col_off = (sub >> 1) * 8;
#pragma unroll
        for (int mt = 0; mt < 2; mt++) {
            const int row = warp * 32 + mt * 16 + row_off;
#pragma unroll
            for (int ks = 0; ks < 4; ks++)
                ldsm4(ps_u + (uint32_t)(row * AKPH + ks * 16 + col_off) * 2, qf[mt][ks]);
        }
    }
    __syncthreads();

    float oacc[2][8][4];
#pragma unroll
    for (int mt = 0; mt < 2; mt++)
#pragma unroll
        for (int nt = 0; nt < 8; nt++)
#pragma unroll
            for (int j = 0; j < 4; j++) oacc[mt][nt][j] = 0.f;

    float mrow[2][2], lrow[2][2];
#pragma unroll
    for (int mt = 0; mt < 2; mt++) {
        mrow[mt][0] = -1e30f; mrow[mt][1] = -1e30f;
        lrow[mt][0] = 0.f;    lrow[mt][1] = 0.f;
    }

    const int ktend = min(2 * qi + 2, (len + 63) >> 6);
    const float SE = ATT_SCALE * LOG2E_F;
    const int warp_row_end = qi * 128 + warp * 32 + 32;

    auto load_kv = [&](int kt, int bufi) {
        const __half* Kp = Kb + (size_t)(kt * 64) * DHH;
        const __half* Vp = Vb + (size_t)(kt * 64) * DHH;
        __half* Kd = smh + A_KS_OFF + bufi * 64 * AKPH;
        __half* Vd = smh + A_VS_OFF + bufi * 64 * AKPH;
#pragma unroll
        for (int i = 0; i < 4; i++) {
            const int idx = tid + i * 128;
            const int r = idx >> 3, j = idx & 7;
            cp16(Kd + r * AKPH + j * 8, Kp + (size_t)r * DHH + j * 8);
            cp16(Vd + r * AKPH + j * 8, Vp + (size_t)r * DHH + j * 8);
        }
        asm volatile("cp.async.commit_group;\n");
    };

    load_kv(0, 0);

    const int prow = warp * 32 + lq;

    for (int kt = 0; kt < ktend; kt++) {
        const int buf = kt & 1;
        asm volatile("cp.async.wait_group 0;\n");
        __syncthreads();
        if (kt + 1 < ktend) load_kv(kt + 1, buf ^ 1);

        if (kt * 64 >= warp_row_end) continue;

        const uint32_t kt_u = (uint32_t)__cvta_generic_to_shared(smh + A_KS_OFF + buf * 64 * AKPH);
        const uint32_t vt_u = (uint32_t)__cvta_generic_to_shared(smh + A_VS_OFF + buf * 64 * AKPH);

        // ---- S = Q K^T ----
        float s[2][8][4];
#pragma unroll
        for (int mt = 0; mt < 2; mt++)
#pragma unroll
            for (int nt = 0; nt < 8; nt++)
#pragma unroll
                for (int j = 0; j < 4; j++) s[mt][nt][j] = 0.f;
        {
            const int row_off = (sub >> 1) * 8 + l7;
            const int col_off = (sub & 1) * 8;
#pragma unroll
            for (int ks = 0; ks < 4; ks++) {
                const int c = ks * 16 + col_off;
#pragma unroll
                for (int ntp = 0; ntp < 4; ntp++) {
                    uint32_t kf[4];
                    ldsm4(kt_u + (uint32_t)((ntp * 16 + row_off) * AKPH + c) * 2, kf);
                    uint32_t b0[2] = {kf[0], kf[1]};
                    uint32_t b1[2] = {kf[2], kf[3]};
                    mma16n8k16(s[0][2 * ntp],     qf[0][ks], b0);
                    mma16n8k16(s[1][2 * ntp],     qf[1][ks], b0);
                    mma16n8k16(s[0][2 * ntp + 1], qf[0][ks], b1);
                    mma16n8k16(s[1][2 * ntp + 1], qf[1][ks], b1);
                }
            }
        }

        // ---- scale + mask ----
        const bool need_mask = (kt >= 2 * qi) || (((kt + 1) << 6) > len);
#pragma unroll
        for (int mt = 0; mt < 2; mt++) {
            const int qg0 = qi * 128 + warp * 32 + mt * 16 + lq;
#pragma unroll
            for (int nt = 0; nt < 8; nt++) {
#pragma unroll
                for (int j = 0; j < 4; j++) {
                    float v = s[mt][nt][j] * SE;
                    if (need_mask) {
                        const int kg = kt * 64 + nt * 8 + (lr << 1) + (j & 1);
                        const int qg = qg0 + ((j & 2) << 2);
                        if (kg > qg || kg >= len) v = -1e30f;
                    }
                    s[mt][nt][j] = v;
                }
            }
        }

        // ---- softmax + fp16 P store + O rescale ----
#pragma unroll
        for (int mt = 0; mt < 2; mt++) {
            float tA = -1e30f, tB = -1e30f;
#pragma unroll
            for (int nt = 0; nt < 8; nt++) {
                tA = fmaxf(tA, fmaxf(s[mt][nt][0], s[mt][nt][1]));
                tB = fmaxf(tB, fmaxf(s[mt][nt][2], s[mt][nt][3]));
            }
            tA = fmaxf(tA, __shfl_xor_sync(0xffffffffu, tA, 1));
            tA = fmaxf(tA, __shfl_xor_sync(0xffffffffu, tA, 2));
            tB = fmaxf(tB, __shfl_xor_sync(0xffffffffu, tB, 1));
            tB = fmaxf(tB, __shfl_xor_sync(0xffffffffu, tB, 2));
            const float mA = fmaxf(mrow[mt][0], tA), mB = fmaxf(mrow[mt][1], tB);
            const float aA = exp2_(mrow[mt][0] - mA), aB = exp2_(mrow[mt][1] - mB);

            float rA = 0.f, rB = 0.f;
            const int pr = prow + mt * 16;
#pragma unroll
            for (int nt = 0; nt < 8; nt++) {
                const float p0 = exp2_(s[mt][nt][0] - mA);
                const float p1 = exp2_(s[mt][nt][1] - mA);
                const float p2 = exp2_(s[mt][nt][2] - mB);
                const float p3 = exp2_(s[mt][nt][3] - mB);
                rA += p0 + p1;
                rB += p2 + p3;
                const int c = nt * 8 + (lr << 1);
                *reinterpret_cast<uint32_t*>(&Ps[pr * AKPH + c]) = packh2(p0, p1);
                *reinterpret_cast<uint32_t*>(&Ps[(pr + 8) * AKPH + c]) = packh2(p2, p3);
            }
            rA += __shfl_xor_sync(0xffffffffu, rA, 1);
            rA += __shfl_xor_sync(0xffffffffu, rA, 2);
            rB += __shfl_xor_sync(0xffffffffu, rB, 1);
            rB += __shfl_xor_sync(0xffffffffu, rB, 2);
            lrow[mt][0] = lrow[mt][0] * aA + rA;
            lrow[mt][1] = lrow[mt][1] * aB + rB;
            mrow[mt][0] = mA;
            mrow[mt][1] = mB;
#pragma unroll
            for (int nt = 0; nt < 8; nt++) {
                oacc[mt][nt][0] *= aA; oacc[mt][nt][1] *= aA;
                oacc[mt][nt][2] *= aB; oacc[mt][nt][3] *= aB;
            }
        }
        __syncwarp();

        // ---- O += P V ----
        {
            const int prow_off = (sub & 1) * 8 + l7;
            const int pcol_off = (sub >> 1) * 8;
#pragma unroll
            for (int ks = 0; ks < 4; ks++) {
                uint32_t pa[2][4];
#pragma unroll
                for (int mt = 0; mt < 2; mt++) {
                    const int row = warp * 32 + mt * 16 + prow_off;
                    ldsm4(ps_u + (uint32_t)(row * AKPH + ks * 16 + pcol_off) * 2, pa[mt]);
                }
#pragma unroll
                for (int ntp = 0; ntp < 4; ntp++) {
                    const int row = ks * 16 + ((lane >> 3) & 1) * 8 + (lane & 7);
                    const int col = ntp * 16 + ((lane >> 4) << 3);
                    uint32_t vf[4];
                    ldsm4t(vt_u + (uint32_t)(row * AKPH + col) * 2, vf);
                    uint32_t b0[2] = {vf[0], vf[1]}, b1[2] = {vf[2], vf[3]};
                    mma16n8k16(oacc[0][2 * ntp],     pa[0], b0);
                    mma16n8k16(oacc[1][2 * ntp],     pa[1], b0);
                    mma16n8k16(oacc[0][2 * ntp + 1], pa[0], b1);
                    mma16n8k16(oacc[1][2 * ntp + 1], pa[1], b1);
                }
            }
        }
        __syncwarp();
    }

    // ---- finalize: fp16 O in [b,t,h*64+dh] ----
    __half* __restrict__ Ob = g_O + ((size_t)b * TT) * DD + h * DHH;
#pragma unroll
    for (int mt = 0; mt < 2; mt++) {
        const float invA = 1.f / lrow[mt][0], invB = 1.f / lrow[mt][1];
        const int q0 = qi * 128 + warp * 32 + mt * 16 + lq;
#pragma unroll
        for (int nt = 0; nt < 8; nt++) {
            const int dh = nt * 8 + (lr << 1);
            *reinterpret_cast<uint32_t*>(&Ob[(size_t)q0 * DD + dh]) =
                packh2(oacc[mt][nt][0] * invA, oacc[mt][nt][1] * invA);
            *reinterpret_cast<uint32_t*>(&Ob[(size_t)(q0 + 8) * DD + dh]) =
                packh2(oacc[mt][nt][2] * invB, oacc[mt][nt][3] * invB);
        }
    }
}

// ---------------------------------------------------------------------------
// Launch
// ---------------------------------------------------------------------------
extern "C" void kernel_launch(void* const* d_in, const int* in_sizes, int n_in,
                              void* d_out, int out_size)
{
    const float* big[4] = {nullptr, nullptr, nullptr, nullptr};
    const float* w[4]   = {nullptr, nullptr, nullptr, nullptr};
    const unsigned char* kpm = nullptr;
    int nbig = 0, nw = 0;
    for (int i = 0; i < n_in; i++) {
        if (in_sizes[i] == TT * TT && nbig < 4) big[nbig++] = (const float*)d_in[i];
        else if (in_sizes[i] == DD * DD && nw < 4) w[nw++] = (const float*)d_in[i];
        else if (in_sizes[i] == BB * TT) kpm = (const unsigned char*)d_in[i];
    }
    const float* query = big[0];
    const float* key_t = big[1];
    const float* value = big[2];
    const float* Wq = w[0];
    const float* Wk = w[1];
    const float* Wv = w[2];
    const float* Wo = w[3];
    float* out = (float*)d_out;

    static bool attr_set = false;
    if (!attr_set) {
        cudaFuncSetAttribute(proj_qkv_kernel, cudaFuncAttributeMaxDynamicSharedMemorySize, PSMEM);
        cudaFuncSetAttribute(proj_o_kernel, cudaFuncAttributeMaxDynamicSharedMemorySize, PSMEM);
        cudaFuncSetAttribute(attn_kernel, cudaFuncAttributeMaxDynamicSharedMemorySize, A_SMEM);
        attr_set = true;
    }

    lens_kernel<<<BB, 256>>>(kpm);
    round_kernel<<<dim3((MM * DD) / 4 / 256, 7), 256>>>(query, key_t, value, Wq, Wk, Wv, Wo);
    proj_qkv_kernel<<<dim3(DD / PBN, MM / PBM, 3), 128, PSMEM>>>();
    attn_kernel<<<dim3(TT / 128, HH, BB), 128, A_SMEM>>>();
    proj_o_kernel<<<dim3(DD / PBN, MM / PBM, 1), 128, PSMEM>>>(out);
}

// round 12
// speedup vs baseline: 1.8207x; 1.0160x over previous
#include <cuda_runtime.h>
#include <cuda_fp16.h>
#include <cstdint>

// Problem constants
#define BB   2
#define TT   2048
#define DD   1024
#define HH   16
#define DHH  64
#define MM   (BB*TT)          // 4096
#define ATT_SCALE 0.125f      // DH^-0.5
#define LOG2E_F 1.4426950408889634f

// ---------------------------------------------------------------------------
// Scratch (allocation-free: __device__ globals), all fp16
// ---------------------------------------------------------------------------
__device__ __align__(256) __half g_Q[BB*HH*TT*DHH];   // [b,h,t,dh]
__device__ __align__(256) __half g_K[BB*HH*TT*DHH];
__device__ __align__(256) __half g_V[BB*HH*TT*DHH];
__device__ __align__(256) __half g_O[MM*DD];          // [b,t,h*64+dh]
__device__ __align__(256) __half g_RIN[3*MM*DD];      // fp16 query,key,value
__device__ __align__(256) __half g_RW[4*DD*DD];       // fp16 Wq,Wk,Wv,Wo
__device__ int   g_len[BB];

// ---------------------------------------------------------------------------
// Helpers
// ---------------------------------------------------------------------------
__device__ __forceinline__ float exp2_(float x) {
    float r;
    asm("ex2.approx.ftz.f32 %0, %1;" : "=f"(r) : "f"(x));
    return r;
}
__device__ __forceinline__ uint32_t packh2(float a, float b) {
    __half2 h = __floats2half2_rn(a, b);
    return *reinterpret_cast<uint32_t*>(&h);
}
__device__ __forceinline__ void mma16n8k16(float c[4], const uint32_t a[4], const uint32_t b[2]) {
    asm volatile("mma.sync.aligned.m16n8k16.row.col.f32.f16.f16.f32 "
        "{%0,%1,%2,%3}, {%4,%5,%6,%7}, {%8,%9}, {%0,%1,%2,%3};\n"
        : "+f"(c[0]), "+f"(c[1]), "+f"(c[2]), "+f"(c[3])
        : "r"(a[0]), "r"(a[1]), "r"(a[2]), "r"(a[3]), "r"(b[0]), "r"(b[1]));
}
__device__ __forceinline__ void cp16(void* s, const void* g) {
    uint32_t sa = (uint32_t)__cvta_generic_to_shared(s);
    asm volatile("cp.async.cg.shared.global [%0], [%1], 16;\n" :: "r"(sa), "l"(g));
}
__device__ __forceinline__ void ldsm4(uint32_t addr, uint32_t r[4]) {
    asm volatile("ldmatrix.sync.aligned.m8n8.x4.shared.b16 {%0,%1,%2,%3}, [%4];"
        : "=r"(r[0]), "=r"(r[1]), "=r"(r[2]), "=r"(r[3]) : "r"(addr));
}
__device__ __forceinline__ void ldsm4t(uint32_t addr, uint32_t r[4]) {
    asm volatile("ldmatrix.sync.aligned.m8n8.x4.trans.shared.b16 {%0,%1,%2,%3}, [%4];"
        : "=r"(r[0]), "=r"(r[1]), "=r"(r[2]), "=r"(r[3]) : "r"(addr));
}

// ---------------------------------------------------------------------------
// lens kernel (padding length per batch)
// ---------------------------------------------------------------------------
__global__ void lens_kernel(const unsigned char* __restrict__ kpm) {
    __shared__ int sred[256];
    const int b = blockIdx.x;
    const bool is_u8 = (kpm[TT - 1] != 0);
    int cnt = 0;
    if (is_u8) {
        const unsigned char* row = kpm + (size_t)b * TT;
        for (int t = threadIdx.x; t < TT; t += 256) cnt += (row[t] == 0);
    } else {
        const int* row = reinterpret_cast<const int*>(kpm) + (size_t)b * TT;
        for (int t = threadIdx.x; t < TT; t += 256) cnt += (row[t] == 0);
    }
    sred[threadIdx.x] = cnt;
    __syncthreads();
    for (int s = 128; s > 0; s >>= 1) {
        if (threadIdx.x < s) sred[threadIdx.x] += sred[threadIdx.x + s];
        __syncthreads();
    }
    if (threadIdx.x == 0) g_len[b] = sred[0];
}

// ---------------------------------------------------------------------------
// Convert inputs + weights to fp16 (RN).
// ---------------------------------------------------------------------------
__global__ void __launch_bounds__(256) round_kernel(
    const float* __restrict__ q, const float* __restrict__ k, const float* __restrict__ v,
    const float* __restrict__ wq, const float* __restrict__ wk,
    const float* __restrict__ wv, const float* __restrict__ wo)
{
    const int y = blockIdx.y;
    const float* src; __half* dst; int n4;
    if (y < 3) {
        src = (y == 0) ? q : (y == 1) ? k : v;
        dst = g_RIN + (size_t)y * (MM * DD);
        n4 = (MM * DD) / 4;
    } else {
        src = (y == 3) ? wq : (y == 4) ? wk : (y == 5) ? wv : wo;
        dst = g_RW + (size_t)(y - 3) * (DD * DD);
        n4 = (DD * DD) / 4;
    }
    const int i = blockIdx.x * 256 + threadIdx.x;
    if (i >= n4) return;
    float4 x = reinterpret_cast<const float4*>(src)[i];
    uint2 o;
    o.x = packh2(x.x, x.y);
    o.y = packh2(x.z, x.w);
    reinterpret_cast<uint2*>(dst)[i] = o;
}

// ---------------------------------------------------------------------------
// FP16 mma.sync GEMM with LDSM operand loads (unchanged from R11).
// ---------------------------------------------------------------------------
#define PBM 128
#define PBN 128
#define PBK 32
#define PPDH 40
#define PNKT (DD / PBK)
#define PASZH (PBM * PPDH)
#define PSMEM (4 * PASZH * 2)

template<int MODE>   // 0: fp16 head-major out; 1: fp32 row-major out
__device__ __forceinline__ void gemm_body(const __half* __restrict__ A,
                                          const __half* __restrict__ W,
                                          void* __restrict__ outp)
{
    extern __shared__ __half smh[];
    __half* As = smh;
    __half* Bs = smh + 2 * PASZH;

    const int tid  = threadIdx.x;
    const int lane = tid & 31, warp = tid >> 5;
    const int wm = warp >> 1, wn = warp & 1;
    const int bm = blockIdx.y * PBM, bn = blockIdx.x * PBN;
    const int lq = lane >> 2, lr = lane & 3;
    const int sub = lane >> 3, l7 = lane & 7;

    float acc[4][8][4];
#pragma unroll
    for (int mt = 0; mt < 4; mt++)
#pragma unroll
        for (int nt = 0; nt < 8; nt++)
#pragma unroll
            for (int j = 0; j < 4; j++) acc[mt][nt][j] = 0.f;

    const __half* Abase = A + (size_t)bm * DD;
    const __half* Wbase = W + (size_t)bn * DD;

    auto load_tile = [&](int kt, int buf) {
        const int k0 = kt * PBK;
#pragma unroll
        for (int i = 0; i < 4; i++) {
            const int idx = tid + i * 128;
            const int r = idx >> 2, j = idx & 3;
            cp16(&As[buf * PASZH + r * PPDH + j * 8], Abase + (size_t)r * DD + k0 + j * 8);
        }
#pragma unroll
        for (int i = 0; i < 4; i++) {
            const int idx = tid + i * 128;
            const int r = idx >> 2, j = idx & 3;
            cp16(&Bs[buf * PASZH + r * PPDH + j * 8], Wbase + (size_t)r * DD + k0 + j * 8);
        }
        asm volatile("cp.async.commit_group;\n");
    };

    load_tile(0, 0);

    for (int kt = 0; kt < PNKT; kt++) {
        const int buf = kt & 1;
        if (kt + 1 < PNKT) {
            load_tile(kt + 1, buf ^ 1);
            asm volatile("cp.async.wait_group 1;\n");
        } else {
            asm volatile("cp.async.wait_group 0;\n");
        }
        __syncthreads();

        const uint32_t Abu = (uint32_t)__cvta_generic_to_shared(&As[buf * PASZH]);
        const uint32_t Bbu = (uint32_t)__cvta_generic_to_shared(&Bs[buf * PASZH]);

#pragma unroll
        for (int ks = 0; ks < 2; ks++) {
            const int c = ks * 16;
            uint32_t af[4][4], bfq[4][4];
            {
                const int row_off = (sub & 1) * 8 + l7;
                const int col = c + (sub >> 1) * 8;
#pragma unroll
                for (int mt = 0; mt < 4; mt++) {
                    const int row = wm * 64 + mt * 16 + row_off;
                    ldsm4(Abu + (uint32_t)(row * PPDH + col) * 2, af[mt]);
                }
            }
            {
                const int row_off = (sub >> 1) * 8 + l7;
                const int col = c + (sub & 1) * 8;
#pragma unroll
                for (int ntp = 0; ntp < 4; ntp++) {
                    const int row = wn * 64 + ntp * 16 + row_off;
                    ldsm4(Bbu + (uint32_t)(row * PPDH + col) * 2, bfq[ntp]);
                }
            }
#pragma unroll
            for (int ntp = 0; ntp < 4; ntp++) {
                uint32_t b0[2] = {bfq[ntp][0], bfq[ntp][1]};
                uint32_t b1[2] = {bfq[ntp][2], bfq[ntp][3]};
#pragma unroll
                for (int mt = 0; mt < 4; mt++) {
                    mma16n8k16(acc[mt][2 * ntp],     af[mt], b0);
                    mma16n8k16(acc[mt][2 * ntp + 1], af[mt], b1);
                }
            }
        }
        __syncthreads();
    }

#pragma unroll
    for (int mt = 0; mt < 4; mt++) {
        const int gm = bm + wm * 64 + mt * 16 + lq;
#pragma unroll
        for (int nt = 0; nt < 8; nt++) {
            const int gn = bn + wn * 64 + nt * 8 + (lr << 1);
            if (MODE == 0) {
                __half* out = (__half*)outp;
                const int h = gn >> 6, dh = gn & 63;
                const int b0 = gm >> 11, t0 = gm & (TT - 1);
                *reinterpret_cast<uint32_t*>(
                    &out[(((size_t)b0 * HH + h) * TT + t0) * DHH + dh]) =
                    packh2(acc[mt][nt][0], acc[mt][nt][1]);
                const int gm1 = gm + 8;
                const int b1 = gm1 >> 11, t1 = gm1 & (TT - 1);
                *reinterpret_cast<uint32_t*>(
                    &out[(((size_t)b1 * HH + h) * TT + t1) * DHH + dh]) =
                    packh2(acc[mt][nt][2], acc[mt][nt][3]);
            } else {
                float* out = (float*)outp;
                *reinterpret_cast<float2*>(&out[(size_t)gm * DD + gn]) =
                    make_float2(acc[mt][nt][0], acc[mt][nt][1]);
                *reinterpret_cast<float2*>(&out[(size_t)(gm + 8) * DD + gn]) =
                    make_float2(acc[mt][nt][2], acc[mt][nt][3]);
            }
        }
    }
}

__global__ void __launch_bounds__(128, 2)
proj_qkv_kernel()
{
    const int z = blockIdx.z;
    const __half* A = g_RIN + (size_t)z * (MM * DD);
    const __half* W = g_RW + (size_t)z * (DD * DD);
    __half* out = (z == 0) ? g_Q : (z == 1) ? g_K : g_V;
    gemm_body<0>(A, W, out);
}

__global__ void __launch_bounds__(128, 2)
proj_o_kernel(float* __restrict__ out)
{
    gemm_body<1>(g_O, g_RW + 3 * (size_t)(DD * DD), out);
}

// ---------------------------------------------------------------------------
// FP16 flash attention v3: 64 q-rows/CTA, 4 warps x 16 rows, ~130 regs,
// 4 CTAs/SM. 64-key tiles double-buffered, LDSM everywhere.
// ---------------------------------------------------------------------------
#define AKPH 72                          // half pitch (144 B)
#define A_KS_OFF 0                       // Ks[2][64][72] = 9216 halves
#define A_VS_OFF 9216                    // Vs[2][64][72] = 9216 halves
#define A_PS_OFF 18432                   // Ps[64][72]    = 4608 halves
#define A_SMEM   ((18432 + 4608) * 2)    // 46,080 B

__global__ void __launch_bounds__(128, 4) attn_kernel()
{
    extern __shared__ __half smh[];
    __half* Ps = smh + A_PS_OFF;

    const int qi = blockIdx.x, h = blockIdx.y, b = blockIdx.z;
    const int tid = threadIdx.x, warp = tid >> 5, lane = tid & 31;
    const int len = g_len[b];
    const int lq = lane >> 2, lr = lane & 3;
    const int sub = lane >> 3, l7 = lane & 7;

    const size_t base = ((size_t)b * HH + h) * TT * DHH;
    const __half* __restrict__ Qb = g_Q + base;
    const __half* __restrict__ Kb = g_K + base;
    const __half* __restrict__ Vb = g_V + base;

    const uint32_t ps_u = (uint32_t)__cvta_generic_to_shared(Ps);

    // ---- stage Q tile (64 x 64), then LDSM fragments ----
#pragma unroll
    for (int i = 0; i < 4; i++) {
        const int idx = tid + i * 128;
        const int r = idx >> 3, j = idx & 7;
        *reinterpret_cast<uint4*>(&Ps[r * AKPH + j * 8]) =
            *reinterpret_cast<const uint4*>(&Qb[(size_t)(qi * 64 + r) * DHH + j * 8]);
    }
    __syncthreads();

    uint32_t qf[4][4];
    {
        const int row = warp * 16 + (sub & 1) * 8 + l7;
        const int col_off = (sub >> 1) * 8;
#pragma unroll
        for (int ks = 0; ks < 4; ks++)
            ldsm4(ps_u + (uint32_t)(row * AKPH + ks * 16 + col_off) * 2, qf[ks]);
    }
    __syncthreads();

    float oacc[8][4];
#pragma unroll
    for (int nt = 0; nt < 8; nt++)
#pragma unroll
        for (int j = 0; j < 4; j++) oacc[nt][j] = 0.f;

    float mrowA = -1e30f, mrowB = -1e30f;
    float lrowA = 0.f, lrowB = 0.f;

    const int ktend = min(qi + 1, (len + 63) >> 6);
    const float SE = ATT_SCALE * LOG2E_F;

    auto load_kv = [&](int kt, int bufi) {
        const __half* Kp = Kb + (size_t)(kt * 64) * DHH;
        const __half* Vp = Vb + (size_t)(kt * 64) * DHH;
        __half* Kd = smh + A_KS_OFF + bufi * 64 * AKPH;
        __half* Vd = smh + A_VS_OFF + bufi * 64 * AKPH;
#pragma unroll
        for (int i = 0; i < 4; i++) {
            const int idx = tid + i * 128;
            const int r = idx >> 3, j = idx & 7;
            cp16(Kd + r * AKPH + j * 8, Kp + (size_t)r * DHH + j * 8);
            cp16(Vd + r * AKPH + j * 8, Vp + (size_t)r * DHH + j * 8);
        }
        asm volatile("cp.async.commit_group;\n");
    };

    load_kv(0, 0);

    const int prow = warp * 16 + lq;

    for (int kt = 0; kt < ktend; kt++) {
        const int buf = kt & 1;
        asm volatile("cp.async.wait_group 0;\n");
        __syncthreads();
        if (kt + 1 < ktend) load_kv(kt + 1, buf ^ 1);

        const uint32_t kt_u = (uint32_t)__cvta_generic_to_shared(smh + A_KS_OFF + buf * 64 * AKPH);
        const uint32_t vt_u = (uint32_t)__cvta_generic_to_shared(smh + A_VS_OFF + buf * 64 * AKPH);

        // ---- S = Q K^T ----
        float s[8][4];
#pragma unroll
        for (int nt = 0; nt < 8; nt++)
#pragma unroll
            for (int j = 0; j < 4; j++) s[nt][j] = 0.f;
        {
            const int row_off = (sub >> 1) * 8 + l7;
            const int col_off = (sub & 1) * 8;
#pragma unroll
            for (int ks = 0; ks < 4; ks++) {
                const int c = ks * 16 + col_off;
#pragma unroll
                for (int ntp = 0; ntp < 4; ntp++) {
                    uint32_t kf[4];
                    ldsm4(kt_u + (uint32_t)((ntp * 16 + row_off) * AKPH + c) * 2, kf);
                    uint32_t b0[2] = {kf[0], kf[1]};
                    uint32_t b1[2] = {kf[2], kf[3]};
                    mma16n8k16(s[2 * ntp],     qf[ks], b0);
                    mma16n8k16(s[2 * ntp + 1], qf[ks], b1);
                }
            }
        }

        // ---- scale + mask ----
        const bool need_mask = (kt == qi) || (((kt + 1) << 6) > len);
        if (need_mask) {
            const int qg0 = qi * 64 + warp * 16 + lq;
#pragma unroll
            for (int nt = 0; nt < 8; nt++) {
#pragma unroll
                for (int j = 0; j < 4; j++) {
                    float v = s[nt][j] * SE;
                    const int kg = kt * 64 + nt * 8 + (lr << 1) + (j & 1);
                    const int qg = qg0 + ((j & 2) << 2);
                    if (kg > qg || kg >= len) v = -1e30f;
                    s[nt][j] = v;
                }
            }
        } else {
#pragma unroll
            for (int nt = 0; nt < 8; nt++)
#pragma unroll
                for (int j = 0; j < 4; j++) s[nt][j] *= SE;
        }

        // ---- online softmax + fp16 P store + O rescale ----
        {
            float tA = -1e30f, tB = -1e30f;
#pragma unroll
            for (int nt = 0; nt < 8; nt++) {
                tA = fmaxf(tA, fmaxf(s[nt][0], s[nt][1]));
                tB = fmaxf(tB, fmaxf(s[nt][2], s[nt][3]));
            }
            tA = fmaxf(tA, __shfl_xor_sync(0xffffffffu, tA, 1));
            tA = fmaxf(tA, __shfl_xor_sync(0xffffffffu, tA, 2));
            tB = fmaxf(tB, __shfl_xor_sync(0xffffffffu, tB, 1));
            tB = fmaxf(tB, __shfl_xor_sync(0xffffffffu, tB, 2));
            const float mA = fmaxf(mrowA, tA), mB = fmaxf(mrowB, tB);
            const float aA = exp2_(mrowA - mA), aB = exp2_(mrowB - mB);

            float rA = 0.f, rB = 0.f;
#pragma unroll
            for (int nt = 0; nt < 8; nt++) {
                const float p0 = exp2_(s[nt][0] - mA);
                const float p1 = exp2_(s[nt][1] - mA);
                const float p2 = exp2_(s[nt][2] - mB);
                const float p3 = exp2_(s[nt][3] - mB);
                rA += p0 + p1;
                rB += p2 + p3;
                const int c = nt * 8 + (lr << 1);
                *reinterpret_cast<uint32_t*>(&Ps[prow * AKPH + c]) = packh2(p0, p1);
                *reinterpret_cast<uint32_t*>(&Ps[(prow + 8) * AKPH + c]) = packh2(p2, p3);
            }
            rA += __shfl_xor_sync(0xffffffffu, rA, 1);
            rA += __shfl_xor_sync(0xffffffffu, rA, 2);
            rB += __shfl_xor_sync(0xffffffffu, rB, 1);
            rB += __shfl_xor_sync(0xffffffffu, rB, 2);
            lrowA = lrowA * aA + rA;
            lrowB = lrowB * aB + rB;
            mrowA = mA;
            mrowB = mB;
#pragma unroll
            for (int nt = 0; nt < 8; nt++) {
                oacc[nt][0] *= aA; oacc[nt][1] *= aA;
                oacc[nt][2] *= aB; oacc[nt][3] *= aB;
            }
        }
        __syncwarp();

        // ---- O += P V ----
        {
            const int prow_off = warp * 16 + (sub & 1) * 8 + l7;
            const int pcol_off = (sub >> 1) * 8;
#pragma unroll
            for (int ks = 0; ks < 4; ks++) {
                uint32_t pa[4];
                ldsm4(ps_u + (uint32_t)(prow_off * AKPH + ks * 16 + pcol_off) * 2, pa);
#pragma unroll
                for (int ntp = 0; ntp < 4; ntp++) {
                    const int row = ks * 16 + ((lane >> 3) & 1) * 8 + (lane & 7);
                    const int col = ntp * 16 + ((lane >> 4) << 3);
                    uint32_t vf[4];
                    ldsm4t(vt_u + (uint32_t)(row * AKPH + col) * 2, vf);
                    uint32_t b0[2] = {vf[0], vf[1]}, b1[2] = {vf[2], vf[3]};
                    mma16n8k16(oacc[2 * ntp],     pa, b0);
                    mma16n8k16(oacc[2 * ntp + 1], pa, b1);
                }
            }
        }
        __syncwarp();
    }

    // ---- finalize: fp16 O in [b,t,h*64+dh] ----
    __half* __restrict__ Ob = g_O + ((size_t)b * TT) * DD + h * DHH;
    {
        const float invA = 1.f / lrowA, invB = 1.f / lrowB;
        const int q0 = qi * 64 + warp * 16 + lq;
#pragma unroll
        for (int nt = 0; nt < 8; nt++) {
            const int dh = nt * 8 + (lr << 1);
            *reinterpret_cast<uint32_t*>(&Ob[(size_t)q0 * DD + dh]) =
                packh2(oacc[nt][0] * invA, oacc[nt][1] * invA);
            *reinterpret_cast<uint32_t*>(&Ob[(size_t)(q0 + 8) * DD + dh]) =
                packh2(oacc[nt][2] * invB, oacc[nt][3] * invB);
        }
    }
}

// ---------------------------------------------------------------------------
// Launch
// ---------------------------------------------------------------------------
extern "C" void kernel_launch(void* const* d_in, const int* in_sizes, int n_in,
                              void* d_out, int out_size)
{
    const float* big[4] = {nullptr, nullptr, nullptr, nullptr};
    const float* w[4]   = {nullptr, nullptr, nullptr, nullptr};
    const unsigned char* kpm = nullptr;
    int nbig = 0, nw = 0;
    for (int i = 0; i < n_in; i++) {
        if (in_sizes[i] == TT * TT && nbig < 4) big[nbig++] = (const float*)d_in[i];
        else if (in_sizes[i] == DD * DD && nw < 4) w[nw++] = (const float*)d_in[i];
        else if (in_sizes[i] == BB * TT) kpm = (const unsigned char*)d_in[i];
    }
    const float* query = big[0];
    const float* key_t = big[1];
    const float* value = big[2];
    const float* Wq = w[0];
    const float* Wk = w[1];
    const float* Wv = w[2];
    const float* Wo = w[3];
    float* out = (float*)d_out;

    static bool attr_set = false;
    if (!attr_set) {
        cudaFuncSetAttribute(proj_qkv_kernel, cudaFuncAttributeMaxDynamicSharedMemorySize, PSMEM);
        cudaFuncSetAttribute(proj_o_kernel, cudaFuncAttributeMaxDynamicSharedMemorySize, PSMEM);
        cudaFuncSetAttribute(attn_kernel, cudaFuncAttributeMaxDynamicSharedMemorySize, A_SMEM);
        attr_set = true;
    }

    lens_kernel<<<BB, 256>>>(kpm);
    round_kernel<<<dim3((MM * DD) / 4 / 256, 7), 256>>>(query, key_t, value, Wq, Wk, Wv, Wo);
    proj_qkv_kernel<<<dim3(DD / PBN, MM / PBM, 3), 128, PSMEM>>>();
    attn_kernel<<<dim3(TT / 64, HH, BB), 128, A_SMEM>>>();
    proj_o_kernel<<<dim3(DD / PBN, MM / PBM, 1), 128, PSMEM>>>(out);
}

// round 13
// speedup vs baseline: 1.9335x; 1.0620x over previous
#include <cuda_runtime.h>
#include <cuda_fp16.h>
#include <cstdint>

// Problem constants
#define BB   2
#define TT   2048
#define DD   1024
#define HH   16
#define DHH  64
#define MM   (BB*TT)          // 4096
#define ATT_SCALE 0.125f      // DH^-0.5
#define LOG2E_F 1.4426950408889634f

// ---------------------------------------------------------------------------
// Scratch (allocation-free: __device__ globals), all fp16
// ---------------------------------------------------------------------------
__device__ __align__(256) __half g_Q[BB*HH*TT*DHH];   // [b,h,t,dh]
__device__ __align__(256) __half g_K[BB*HH*TT*DHH];
__device__ __align__(256) __half g_V[BB*HH*TT*DHH];
__device__ __align__(256) __half g_O[MM*DD];          // [b,t,h*64+dh]
__device__ __align__(256) __half g_RW[4*DD*DD];       // fp16 Wq,Wk,Wv,Wo
__device__ int   g_len[BB];

// ---------------------------------------------------------------------------
// Helpers
// ---------------------------------------------------------------------------
__device__ __forceinline__ float exp2_(float x) {
    float r;
    asm("ex2.approx.ftz.f32 %0, %1;" : "=f"(r) : "f"(x));
    return r;
}
__device__ __forceinline__ uint32_t packh2(float a, float b) {
    __half2 h = __floats2half2_rn(a, b);
    return *reinterpret_cast<uint32_t*>(&h);
}
__device__ __forceinline__ void mma16n8k16(float c[4], const uint32_t a[4], const uint32_t b[2]) {
    asm volatile("mma.sync.aligned.m16n8k16.row.col.f32.f16.f16.f32 "
        "{%0,%1,%2,%3}, {%4,%5,%6,%7}, {%8,%9}, {%0,%1,%2,%3};\n"
        : "+f"(c[0]), "+f"(c[1]), "+f"(c[2]), "+f"(c[3])
        : "r"(a[0]), "r"(a[1]), "r"(a[2]), "r"(a[3]), "r"(b[0]), "r"(b[1]));
}
__device__ __forceinline__ void cp16(void* s, const void* g) {
    uint32_t sa = (uint32_t)__cvta_generic_to_shared(s);
    asm volatile("cp.async.cg.shared.global [%0], [%1], 16;\n" :: "r"(sa), "l"(g));
}
__device__ __forceinline__ void ldsm4(uint32_t addr, uint32_t r[4]) {
    asm volatile("ldmatrix.sync.aligned.m8n8.x4.shared.b16 {%0,%1,%2,%3}, [%4];"
        : "=r"(r[0]), "=r"(r[1]), "=r"(r[2]), "=r"(r[3]) : "r"(addr));
}
__device__ __forceinline__ void ldsm4t(uint32_t addr, uint32_t r[4]) {
    asm volatile("ldmatrix.sync.aligned.m8n8.x4.trans.shared.b16 {%0,%1,%2,%3}, [%4];"
        : "=r"(r[0]), "=r"(r[1]), "=r"(r[2]), "=r"(r[3]) : "r"(addr));
}

// ---------------------------------------------------------------------------
// lens kernel (padding length per batch)
// ---------------------------------------------------------------------------
__global__ void lens_kernel(const unsigned char* __restrict__ kpm) {
    __shared__ int sred[256];
    const int b = blockIdx.x;
    const bool is_u8 = (kpm[TT - 1] != 0);
    int cnt = 0;
    if (is_u8) {
        const unsigned char* row = kpm + (size_t)b * TT;
        for (int t = threadIdx.x; t < TT; t += 256) cnt += (row[t] == 0);
    } else {
        const int* row = reinterpret_cast<const int*>(kpm) + (size_t)b * TT;
        for (int t = threadIdx.x; t < TT; t += 256) cnt += (row[t] == 0);
    }
    sred[threadIdx.x] = cnt;
    __syncthreads();
    for (int s = 128; s > 0; s >>= 1) {
        if (threadIdx.x < s) sred[threadIdx.x] += sred[threadIdx.x + s];
        __syncthreads();
    }
    if (threadIdx.x == 0) g_len[b] = sred[0];
}

// ---------------------------------------------------------------------------
// Convert WEIGHTS ONLY to fp16 (inputs converted inside the QKV GEMM).
// ---------------------------------------------------------------------------
__global__ void __launch_bounds__(256) round_kernel(
    const float* __restrict__ wq, const float* __restrict__ wk,
    const float* __restrict__ wv, const float* __restrict__ wo)
{
    const int y = blockIdx.y;
    const float* src = (y == 0) ? wq : (y == 1) ? wk : (y == 2) ? wv : wo;
    __half* dst = g_RW + (size_t)y * (DD * DD);
    const int i = blockIdx.x * 256 + threadIdx.x;
    float4 x = reinterpret_cast<const float4*>(src)[i];
    uint2 o;
    o.x = packh2(x.x, x.y);
    o.y = packh2(x.z, x.w);
    reinterpret_cast<uint2*>(dst)[i] = o;
}

// ---------------------------------------------------------------------------
// Shared GEMM tile geometry
// ---------------------------------------------------------------------------
#define PBM 128
#define PBN 128
#define PBK 32
#define PPDH 40
#define PNKT (DD / PBK)
#define PASZH (PBM * PPDH)
#define PSMEM (4 * PASZH * 2)

// ---------------------------------------------------------------------------
// QKV GEMM: A is fp32 in gmem (query/key/value), converted to fp16 during
// staging (LDG.128 -> cvt -> STS), register-double-buffered. B (weights)
// pre-converted fp16 via cp.async. Out: fp16 head-major.
// ---------------------------------------------------------------------------
__global__ void __launch_bounds__(128, 2)
proj_qkv_kernel(const float* __restrict__ qin, const float* __restrict__ kin,
                const float* __restrict__ vin)
{
    extern __shared__ __half smh[];
    __half* As = smh;
    __half* Bs = smh + 2 * PASZH;

    const int z = blockIdx.z;
    const float* A = (z == 0) ? qin : (z == 1) ? kin : vin;
    const __half* W = g_RW + (size_t)z * (DD * DD);
    __half* out = (z == 0) ? g_Q : (z == 1) ? g_K : g_V;

    const int tid  = threadIdx.x;
    const int lane = tid & 31, warp = tid >> 5;
    const int wm = warp >> 1, wn = warp & 1;
    const int bm = blockIdx.y * PBM, bn = blockIdx.x * PBN;
    const int lq = lane >> 2, lr = lane & 3;
    const int sub = lane >> 3, l7 = lane & 7;

    float acc[4][8][4];
#pragma unroll
    for (int mt = 0; mt < 4; mt++)
#pragma unroll
        for (int nt = 0; nt < 8; nt++)
#pragma unroll
            for (int j = 0; j < 4; j++) acc[mt][nt][j] = 0.f;

    const float* Abase = A + (size_t)bm * DD;
    const __half* Wbase = W + (size_t)bn * DD;

    // A staging: 128 rows x 8 float4 per tile; 8 float4 per thread.
    const int ar = tid >> 3;          // rows ar, ar+16, ... (8 rows total? no:)
    const int aj = tid & 7;           // float4 column 0..7
    float4 areg[8];

    auto ldgA = [&](int kt) {
        const int k0 = kt * PBK;
#pragma unroll
        for (int i = 0; i < 8; i++) {
            const int r = (tid >> 3) + i * 16;
            areg[i] = *reinterpret_cast<const float4*>(Abase + (size_t)r * DD + k0 + aj * 4);
        }
    };
    auto stsA = [&](int buf) {
#pragma unroll
        for (int i = 0; i < 8; i++) {
            const int r = (tid >> 3) + i * 16;
            uint2 o;
            o.x = packh2(areg[i].x, areg[i].y);
            o.y = packh2(areg[i].z, areg[i].w);
            *reinterpret_cast<uint2*>(&As[buf * PASZH + r * PPDH + aj * 4]) = o;
        }
    };
    auto cpB = [&](int kt, int buf) {
        const int k0 = kt * PBK;
#pragma unroll
        for (int i = 0; i < 4; i++) {
            const int idx = tid + i * 128;
            const int r = idx >> 2, j = idx & 3;
            cp16(&Bs[buf * PASZH + r * PPDH + j * 8], Wbase + (size_t)r * DD + k0 + j * 8);
        }
        asm volatile("cp.async.commit_group;\n");
    };

    // prologue: tile 0 fully staged; A tile 1 in regs
    ldgA(0);
    stsA(0);
    cpB(0, 0);
    ldgA(1);

    for (int kt = 0; kt < PNKT; kt++) {
        const int buf = kt & 1;
        asm volatile("cp.async.wait_group 0;\n");
        __syncthreads();

        if (kt + 1 < PNKT) {
            cpB(kt + 1, buf ^ 1);
            stsA(buf ^ 1);                 // A(kt+1) regs -> other buffer
            if (kt + 2 < PNKT) ldgA(kt + 2);
        }

        const uint32_t Abu = (uint32_t)__cvta_generic_to_shared(&As[buf * PASZH]);
        const uint32_t Bbu = (uint32_t)__cvta_generic_to_shared(&Bs[buf * PASZH]);

#pragma unroll
        for (int ks = 0; ks < 2; ks++) {
            const int c = ks * 16;
            uint32_t af[4][4], bfq[4][4];
            {
                const int row_off = (sub & 1) * 8 + l7;
                const int col = c + (sub >> 1) * 8;
#pragma unroll
                for (int mt = 0; mt < 4; mt++) {
                    const int row = wm * 64 + mt * 16 + row_off;
                    ldsm4(Abu + (uint32_t)(row * PPDH + col) * 2, af[mt]);
                }
            }
            {
                const int row_off = (sub >> 1) * 8 + l7;
                const int col = c + (sub & 1) * 8;
#pragma unroll
                for (int ntp = 0; ntp < 4; ntp++) {
                    const int row = wn * 64 + ntp * 16 + row_off;
                    ldsm4(Bbu + (uint32_t)(row * PPDH + col) * 2, bfq[ntp]);
                }
            }
#pragma unroll
            for (int ntp = 0; ntp < 4; ntp++) {
                uint32_t b0[2] = {bfq[ntp][0], bfq[ntp][1]};
                uint32_t b1[2] = {bfq[ntp][2], bfq[ntp][3]};
#pragma unroll
                for (int mt = 0; mt < 4; mt++) {
                    mma16n8k16(acc[mt][2 * ntp],     af[mt], b0);
                    mma16n8k16(acc[mt][2 * ntp + 1], af[mt], b1);
                }
            }
        }
    }

    // epilogue: fp16 head-major
#pragma unroll
    for (int mt = 0; mt < 4; mt++) {
        const int gm = bm + wm * 64 + mt * 16 + lq;
#pragma unroll
        for (int nt = 0; nt < 8; nt++) {
            const int gn = bn + wn * 64 + nt * 8 + (lr << 1);
            const int h = gn >> 6, dh = gn & 63;
            const int b0 = gm >> 11, t0 = gm & (TT - 1);
            *reinterpret_cast<uint32_t*>(
                &out[(((size_t)b0 * HH + h) * TT + t0) * DHH + dh]) =
                packh2(acc[mt][nt][0], acc[mt][nt][1]);
            const int gm1 = gm + 8;
            const int b1 = gm1 >> 11, t1 = gm1 & (TT - 1);
            *reinterpret_cast<uint32_t*>(
                &out[(((size_t)b1 * HH + h) * TT + t1) * DHH + dh]) =
                packh2(acc[mt][nt][2], acc[mt][nt][3]);
        }
    }
}

// ---------------------------------------------------------------------------
// O-projection: fp16 A (g_O) via cp.async, fp16 B (Wo), fp32 row-major out.
// ---------------------------------------------------------------------------
__global__ void __launch_bounds__(128, 2)
proj_o_kernel(float* __restrict__ out)
{
    extern __shared__ __half smh[];
    __half* As = smh;
    __half* Bs = smh + 2 * PASZH;

    const __half* A = g_O;
    const __half* W = g_RW + 3 * (size_t)(DD * DD);

    const int tid  = threadIdx.x;
    const int lane = tid & 31, warp = tid >> 5;
    const int wm = warp >> 1, wn = warp & 1;
    const int bm = blockIdx.y * PBM, bn = blockIdx.x * PBN;
    const int lq = lane >> 2, lr = lane & 3;
    const int sub = lane >> 3, l7 = lane & 7;

    float acc[4][8][4];
#pragma unroll
    for (int mt = 0; mt < 4; mt++)
#pragma unroll
        for (int nt = 0; nt < 8; nt++)
#pragma unroll
            for (int j = 0; j < 4; j++) acc[mt][nt][j] = 0.f;

    const __half* Abase = A + (size_t)bm * DD;
    const __half* Wbase = W + (size_t)bn * DD;

    auto load_tile = [&](int kt, int buf) {
        const int k0 = kt * PBK;
#pragma unroll
        for (int i = 0; i < 4; i++) {
            const int idx = tid + i * 128;
            const int r = idx >> 2, j = idx & 3;
            cp16(&As[buf * PASZH + r * PPDH + j * 8], Abase + (size_t)r * DD + k0 + j * 8);
        }
#pragma unroll
        for (int i = 0; i < 4; i++) {
            const int idx = tid + i * 128;
            const int r = idx >> 2, j = idx & 3;
            cp16(&Bs[buf * PASZH + r * PPDH + j * 8], Wbase + (size_t)r * DD + k0 + j * 8);
        }
        asm volatile("cp.async.commit_group;\n");
    };

    load_tile(0, 0);

    for (int kt = 0; kt < PNKT; kt++) {
        const int buf = kt & 1;
        if (kt + 1 < PNKT) {
            load_tile(kt + 1, buf ^ 1);
            asm volatile("cp.async.wait_group 1;\n");
        } else {
            asm volatile("cp.async.wait_group 0;\n");
        }
        __syncthreads();

        const uint32_t Abu = (uint32_t)__cvta_generic_to_shared(&As[buf * PASZH]);
        const uint32_t Bbu = (uint32_t)__cvta_generic_to_shared(&Bs[buf * PASZH]);

#pragma unroll
        for (int ks = 0; ks < 2; ks++) {
            const int c = ks * 16;
            uint32_t af[4][4], bfq[4][4];
            {
                const int row_off = (sub & 1) * 8 + l7;
                const int col = c + (sub >> 1) * 8;
#pragma unroll
                for (int mt = 0; mt < 4; mt++) {
                    const int row = wm * 64 + mt * 16 + row_off;
                    ldsm4(Abu + (uint32_t)(row * PPDH + col) * 2, af[mt]);
                }
            }
            {
                const int row_off = (sub >> 1) * 8 + l7;
                const int col = c + (sub & 1) * 8;
#pragma unroll
                for (int ntp = 0; ntp < 4; ntp++) {
                    const int row = wn * 64 + ntp * 16 + row_off;
                    ldsm4(Bbu + (uint32_t)(row * PPDH + col) * 2, bfq[ntp]);
                }
            }
#pragma unroll
            for (int ntp = 0; ntp < 4; ntp++) {
                uint32_t b0[2] = {bfq[ntp][0], bfq[ntp][1]};
                uint32_t b1[2] = {bfq[ntp][2], bfq[ntp][3]};
#pragma unroll
                for (int mt = 0; mt < 4; mt++) {
                    mma16n8k16(acc[mt][2 * ntp],     af[mt], b0);
                    mma16n8k16(acc[mt][2 * ntp + 1], af[mt], b1);
                }
            }
        }
        __syncthreads();
    }

#pragma unroll
    for (int mt = 0; mt < 4; mt++) {
        const int gm = bm + wm * 64 + mt * 16 + lq;
#pragma unroll
        for (int nt = 0; nt < 8; nt++) {
            const int gn = bn + wn * 64 + nt * 8 + (lr << 1);
            *reinterpret_cast<float2*>(&out[(size_t)gm * DD + gn]) =
                make_float2(acc[mt][nt][0], acc[mt][nt][1]);
            *reinterpret_cast<float2*>(&out[(size_t)(gm + 8) * DD + gn]) =
                make_float2(acc[mt][nt][2], acc[mt][nt][3]);
        }
    }
}

// ---------------------------------------------------------------------------
// FP16 flash attention (unchanged from R12): 64 q-rows/CTA, 4 CTAs/SM.
// ---------------------------------------------------------------------------
#define AKPH 72
#define A_KS_OFF 0
#define A_VS_OFF 9216
#define A_PS_OFF 18432
#define A_SMEM   ((18432 + 4608) * 2)    // 46,080 B

__global__ void __launch_bounds__(128, 4) attn_kernel()
{
    extern __shared__ __half smh[];
    __half* Ps = smh + A_PS_OFF;

    const int qi = blockIdx.x, h = blockIdx.y, b = blockIdx.z;
    const int tid = threadIdx.x, warp = tid >> 5, lane = tid & 31;
    const int len = g_len[b];
    const int lq = lane >> 2, lr = lane & 3;
    const int sub = lane >> 3, l7 = lane & 7;

    const size_t base = ((size_t)b * HH + h) * TT * DHH;
    const __half* __restrict__ Qb = g_Q + base;
    const __half* __restrict__ Kb = g_K + base;
    const __half* __restrict__ Vb = g_V + base;

    const uint32_t ps_u = (uint32_t)__cvta_generic_to_shared(Ps);

#pragma unroll
    for (int i = 0; i < 4; i++) {
        const int idx = tid + i * 128;
        const int r = idx >> 3, j = idx & 7;
        *reinterpret_cast<uint4*>(&Ps[r * AKPH + j * 8]) =
            *reinterpret_cast<const uint4*>(&Qb[(size_t)(qi * 64 + r) * DHH + j * 8]);
    }
    __syncthreads();

    uint32_t qf[4][4];
    {
        const int row = warp * 16 + (sub & 1) * 8 + l7;
        const int col_off = (sub >> 1) * 8;
#pragma unroll
        for (int ks = 0; ks < 4; ks++)
            ldsm4(ps_u + (uint32_t)(row * AKPH + ks * 16 + col_off) * 2, qf[ks]);
    }
    __syncthreads();

    float oacc[8][4];
#pragma unroll
    for (int nt = 0; nt < 8; nt++)
#pragma unroll
        for (int j = 0; j < 4; j++) oacc[nt][j] = 0.f;

    float mrowA = -1e30f, mrowB = -1e30f;
    float lrowA = 0.f, lrowB = 0.f;

    const int ktend = min(qi + 1, (len + 63) >> 6);
    const float SE = ATT_SCALE * LOG2E_F;

    auto load_kv = [&](int kt, int bufi) {
        const __half* Kp = Kb + (size_t)(kt * 64) * DHH;
        const __half* Vp = Vb + (size_t)(kt * 64) * DHH;
        __half* Kd = smh + A_KS_OFF + bufi * 64 * AKPH;
        __half* Vd = smh + A_VS_OFF + bufi * 64 * AKPH;
#pragma unroll
        for (int i = 0; i < 4; i++) {
            const int idx = tid + i * 128;
            const int r = idx >> 3, j = idx & 7;
            cp16(Kd + r * AKPH + j * 8, Kp + (size_t)r * DHH + j * 8);
            cp16(Vd + r * AKPH + j * 8, Vp + (size_t)r * DHH + j * 8);
        }
        asm volatile("cp.async.commit_group;\n");
    };

    load_kv(0, 0);

    const int prow = warp * 16 + lq;

    for (int kt = 0; kt < ktend; kt++) {
        const int buf = kt & 1;
        asm volatile("cp.async.wait_group 0;\n");
        __syncthreads();
        if (kt + 1 < ktend) load_kv(kt + 1, buf ^ 1);

        const uint32_t kt_u = (uint32_t)__cvta_generic_to_shared(smh + A_KS_OFF + buf * 64 * AKPH);
        const uint32_t vt_u = (uint32_t)__cvta_generic_to_shared(smh + A_VS_OFF + buf * 64 * AKPH);

        float s[8][4];
#pragma unroll
        for (int nt = 0; nt < 8; nt++)
#pragma unroll
            for (int j = 0; j < 4; j++) s[nt][j] = 0.f;
        {
            const int row_off = (sub >> 1) * 8 + l7;
            const int col_off = (sub & 1) * 8;
#pragma unroll
            for (int ks = 0; ks < 4; ks++) {
                const int c = ks * 16 + col_off;
#pragma unroll
                for (int ntp = 0; ntp < 4; ntp++) {
                    uint32_t kf[4];
                    ldsm4(kt_u + (uint32_t)((ntp * 16 + row_off) * AKPH + c) * 2, kf);
                    uint32_t b0[2] = {kf[0], kf[1]};
                    uint32_t b1[2] = {kf[2], kf[3]};
                    mma16n8k16(s[2 * ntp],     qf[ks], b0);
                    mma16n8k16(s[2 * ntp + 1], qf[ks], b1);
                }
            }
        }

        const bool need_mask = (kt == qi) || (((kt + 1) << 6) > len);
        if (need_mask) {
            const int qg0 = qi * 64 + warp * 16 + lq;
#pragma unroll
            for (int nt = 0; nt < 8; nt++) {
#pragma unroll
                for (int j = 0; j < 4; j++) {
                    float v = s[nt][j] * SE;
                    const int kg = kt * 64 + nt * 8 + (lr << 1) + (j & 1);
                    const int qg = qg0 + ((j & 2) << 2);
                    if (kg > qg || kg >= len) v = -1e30f;
                    s[nt][j] = v;
                }
            }
        } else {
#pragma unroll
            for (int nt = 0; nt < 8; nt++)
#pragma unroll
                for (int j = 0; j < 4; j++) s[nt][j] *= SE;
        }

        {
            float tA = -1e30f, tB = -1e30f;
#pragma unroll
            for (int nt = 0; nt < 8; nt++) {
                tA = fmaxf(tA, fmaxf(s[nt][0], s[nt][1]));
                tB = fmaxf(tB, fmaxf(s[nt][2], s[nt][3]));
            }
            tA = fmaxf(tA, __shfl_xor_sync(0xffffffffu, tA, 1));
            tA = fmaxf(tA, __shfl_xor_sync(0xffffffffu, tA, 2));
            tB = fmaxf(tB, __shfl_xor_sync(0xffffffffu, tB, 1));
            tB = fmaxf(tB, __shfl_xor_sync(0xffffffffu, tB, 2));
            const float mA = fmaxf(mrowA, tA), mB = fmaxf(mrowB, tB);
            const float aA = exp2_(mrowA - mA), aB = exp2_(mrowB - mB);

            float rA = 0.f, rB = 0.f;
#pragma unroll
            for (int nt = 0; nt < 8; nt++) {
                const float p0 = exp2_(s[nt][0] - mA);
                const float p1 = exp2_(s[nt][1] - mA);
                const float p2 = exp2_(s[nt][2] - mB);
                const float p3 = exp2_(s[nt][3] - mB);
                rA += p0 + p1;
                rB += p2 + p3;
                const int c = nt * 8 + (lr << 1);
                *reinterpret_cast<uint32_t*>(&Ps[prow * AKPH + c]) = packh2(p0, p1);
                *reinterpret_cast<uint32_t*>(&Ps[(prow + 8) * AKPH + c]) = packh2(p2, p3);
            }
            rA += __shfl_xor_sync(0xffffffffu, rA, 1);
            rA += __shfl_xor_sync(0xffffffffu, rA, 2);
            rB += __shfl_xor_sync(0xffffffffu, rB, 1);
            rB += __shfl_xor_sync(0xffffffffu, rB, 2);
            lrowA = lrowA * aA + rA;
            lrowB = lrowB * aB + rB;
            mrowA = mA;
            mrowB = mB;
#pragma unroll
            for (int nt = 0; nt < 8; nt++) {
                oacc[nt][0] *= aA; oacc[nt][1] *= aA;
                oacc[nt][2] *= aB; oacc[nt][3] *= aB;
            }
        }
        __syncwarp();

        {
            const int prow_off = warp * 16 + (sub & 1) * 8 + l7;
            const int pcol_off = (sub >> 1) * 8;
#pragma unroll
            for (int ks = 0; ks < 4; ks++) {
                uint32_t pa[4];
                ldsm4(ps_u + (uint32_t)(prow_off * AKPH + ks * 16 + pcol_off) * 2, pa);
#pragma unroll
                for (int ntp = 0; ntp < 4; ntp++) {
                    const int row = ks * 16 + ((lane >> 3) & 1) * 8 + (lane & 7);
                    const int col = ntp * 16 + ((lane >> 4) << 3);
                    uint32_t vf[4];
                    ldsm4t(vt_u + (uint32_t)(row * AKPH + col) * 2, vf);
                    uint32_t b0[2] = {vf[0], vf[1]}, b1[2] = {vf[2], vf[3]};
                    mma16n8k16(oacc[2 * ntp],     pa, b0);
                    mma16n8k16(oacc[2 * ntp + 1], pa, b1);
                }
            }
        }
        __syncwarp();
    }

    __half* __restrict__ Ob = g_O + ((size_t)b * TT) * DD + h * DHH;
    {
        const float invA = 1.f / lrowA, invB = 1.f / lrowB;
        const int q0 = qi * 64 + warp * 16 + lq;
#pragma unroll
        for (int nt = 0; nt < 8; nt++) {
            const int dh = nt * 8 + (lr << 1);
            *reinterpret_cast<uint32_t*>(&Ob[(size_t)q0 * DD + dh]) =
                packh2(oacc[nt][0] * invA, oacc[nt][1] * invA);
            *reinterpret_cast<uint32_t*>(&Ob[(size_t)(q0 + 8) * DD + dh]) =
                packh2(oacc[nt][2] * invB, oacc[nt][3] * invB);
        }
    }
}

// ---------------------------------------------------------------------------
// Launch
// ---------------------------------------------------------------------------
extern "C" void kernel_launch(void* const* d_in, const int* in_sizes, int n_in,
                              void* d_out, int out_size)
{
    const float* big[4] = {nullptr, nullptr, nullptr, nullptr};
    const float* w[4]   = {nullptr, nullptr, nullptr, nullptr};
    const unsigned char* kpm = nullptr;
    int nbig = 0, nw = 0;
    for (int i = 0; i < n_in; i++) {
        if (in_sizes[i] == TT * TT && nbig < 4) big[nbig++] = (const float*)d_in[i];
        else if (in_sizes[i] == DD * DD && nw < 4) w[nw++] = (const float*)d_in[i];
        else if (in_sizes[i] == BB * TT) kpm = (const unsigned char*)d_in[i];
    }
    const float* query = big[0];
    const float* key_t = big[1];
    const float* value = big[2];
    const float* Wq = w[0];
    const float* Wk = w[1];
    const float* Wv = w[2];
    const float* Wo = w[3];
    float* out = (float*)d_out;

    static bool attr_set = false;
    if (!attr_set) {
        cudaFuncSetAttribute(proj_qkv_kernel, cudaFuncAttributeMaxDynamicSharedMemorySize, PSMEM);
        cudaFuncSetAttribute(proj_o_kernel, cudaFuncAttributeMaxDynamicSharedMemorySize, PSMEM);
        cudaFuncSetAttribute(attn_kernel, cudaFuncAttributeMaxDynamicSharedMemorySize, A_SMEM);
        attr_set = true;
    }

    lens_kernel<<<BB, 256>>>(kpm);
    round_kernel<<<dim3((DD * DD) / 4 / 256, 4), 256>>>(Wq, Wk, Wv, Wo);
    proj_qkv_kernel<<<dim3(DD / PBN, MM / PBM, 3), 128, PSMEM>>>(query, key_t, value);
    attn_kernel<<<dim3(TT / 64, HH, BB), 128, A_SMEM>>>();
    proj_o_kernel<<<dim3(DD / PBN, MM / PBM, 1), 128, PSMEM>>>(out);
}

// round 14
// speedup vs baseline: 1.9650x; 1.0163x over previous
#include <cuda_runtime.h>
#include <cuda_fp16.h>
#include <cstdint>

// Problem constants
#define BB   2
#define TT   2048
#define DD   1024
#define HH   16
#define DHH  64
#define MM   (BB*TT)          // 4096
#define ATT_SCALE 0.125f      // DH^-0.5
#define LOG2E_F 1.4426950408889634f

// ---------------------------------------------------------------------------
// Scratch (allocation-free: __device__ globals), all fp16
// ---------------------------------------------------------------------------
__device__ __align__(256) __half g_Q[BB*HH*TT*DHH];   // [b,h,t,dh]
__device__ __align__(256) __half g_K[BB*HH*TT*DHH];
__device__ __align__(256) __half g_V[BB*HH*TT*DHH];
__device__ __align__(256) __half g_O[MM*DD];          // [b,t,h*64+dh]
__device__ __align__(256) __half g_RW[4*DD*DD];       // fp16 Wq,Wk,Wv,Wo
__device__ int   g_len[BB];

// ---------------------------------------------------------------------------
// Helpers
// ---------------------------------------------------------------------------
__device__ __forceinline__ float exp2_(float x) {
    float r;
    asm("ex2.approx.ftz.f32 %0, %1;" : "=f"(r) : "f"(x));
    return r;
}
__device__ __forceinline__ uint32_t packh2(float a, float b) {
    __half2 h = __floats2half2_rn(a, b);
    return *reinterpret_cast<uint32_t*>(&h);
}
__device__ __forceinline__ uint32_t ex2h2(uint32_t x) {
    uint32_t r;
    asm("ex2.approx.f16x2 %0, %1;" : "=r"(r) : "r"(x));
    return r;
}
__device__ __forceinline__ void mma16n8k16(float c[4], const uint32_t a[4], const uint32_t b[2]) {
    asm volatile("mma.sync.aligned.m16n8k16.row.col.f32.f16.f16.f32 "
        "{%0,%1,%2,%3}, {%4,%5,%6,%7}, {%8,%9}, {%0,%1,%2,%3};\n"
        : "+f"(c[0]), "+f"(c[1]), "+f"(c[2]), "+f"(c[3])
        : "r"(a[0]), "r"(a[1]), "r"(a[2]), "r"(a[3]), "r"(b[0]), "r"(b[1]));
}
__device__ __forceinline__ void cp16(void* s, const void* g) {
    uint32_t sa = (uint32_t)__cvta_generic_to_shared(s);
    asm volatile("cp.async.cg.shared.global [%0], [%1], 16;\n" :: "r"(sa), "l"(g));
}
__device__ __forceinline__ void ldsm4(uint32_t addr, uint32_t r[4]) {
    asm volatile("ldmatrix.sync.aligned.m8n8.x4.shared.b16 {%0,%1,%2,%3}, [%4];"
        : "=r"(r[0]), "=r"(r[1]), "=r"(r[2]), "=r"(r[3]) : "r"(addr));
}
__device__ __forceinline__ void ldsm4t(uint32_t addr, uint32_t r[4]) {
    asm volatile("ldmatrix.sync.aligned.m8n8.x4.trans.shared.b16 {%0,%1,%2,%3}, [%4];"
        : "=r"(r[0]), "=r"(r[1]), "=r"(r[2]), "=r"(r[3]) : "r"(addr));
}

// ---------------------------------------------------------------------------
// lens kernel (padding length per batch)
// ---------------------------------------------------------------------------
__global__ void lens_kernel(const unsigned char* __restrict__ kpm) {
    __shared__ int sred[256];
    const int b = blockIdx.x;
    const bool is_u8 = (kpm[TT - 1] != 0);
    int cnt = 0;
    if (is_u8) {
        const unsigned char* row = kpm + (size_t)b * TT;
        for (int t = threadIdx.x; t < TT; t += 256) cnt += (row[t] == 0);
    } else {
        const int* row = reinterpret_cast<const int*>(kpm) + (size_t)b * TT;
        for (int t = threadIdx.x; t < TT; t += 256) cnt += (row[t] == 0);
    }
    sred[threadIdx.x] = cnt;
    __syncthreads();
    for (int s = 128; s > 0; s >>= 1) {
        if (threadIdx.x < s) sred[threadIdx.x] += sred[threadIdx.x + s];
        __syncthreads();
    }
    if (threadIdx.x == 0) g_len[b] = sred[0];
}

// ---------------------------------------------------------------------------
// Convert WEIGHTS ONLY to fp16 (inputs converted inside the QKV GEMM).
// ---------------------------------------------------------------------------
__global__ void __launch_bounds__(256) round_kernel(
    const float* __restrict__ wq, const float* __restrict__ wk,
    const float* __restrict__ wv, const float* __restrict__ wo)
{
    const int y = blockIdx.y;
    const float* src = (y == 0) ? wq : (y == 1) ? wk : (y == 2) ? wv : wo;
    __half* dst = g_RW + (size_t)y * (DD * DD);
    const int i = blockIdx.x * 256 + threadIdx.x;
    float4 x = reinterpret_cast<const float4*>(src)[i];
    uint2 o;
    o.x = packh2(x.x, x.y);
    o.y = packh2(x.z, x.w);
    reinterpret_cast<uint2*>(dst)[i] = o;
}

// ---------------------------------------------------------------------------
// Shared GEMM tile geometry
// ---------------------------------------------------------------------------
#define PBM 128
#define PBN 128
#define PBK 32
#define PPDH 40
#define PNKT (DD / PBK)
#define PASZH (PBM * PPDH)
#define PSMEM (4 * PASZH * 2)

// ---------------------------------------------------------------------------
// QKV GEMM: A fp32 in gmem, converted to fp16 during staging; B fp16 cp.async.
// ---------------------------------------------------------------------------
__global__ void __launch_bounds__(128, 2)
proj_qkv_kernel(const float* __restrict__ qin, const float* __restrict__ kin,
                const float* __restrict__ vin)
{
    extern __shared__ __half smh[];
    __half* As = smh;
    __half* Bs = smh + 2 * PASZH;

    const int z = blockIdx.z;
    const float* A = (z == 0) ? qin : (z == 1) ? kin : vin;
    const __half* W = g_RW + (size_t)z * (DD * DD);
    __half* out = (z == 0) ? g_Q : (z == 1) ? g_K : g_V;

    const int tid  = threadIdx.x;
    const int lane = tid & 31, warp = tid >> 5;
    const int wm = warp >> 1, wn = warp & 1;
    const int bm = blockIdx.y * PBM, bn = blockIdx.x * PBN;
    const int lq = lane >> 2, lr = lane & 3;
    const int sub = lane >> 3, l7 = lane & 7;

    float acc[4][8][4];
#pragma unroll
    for (int mt = 0; mt < 4; mt++)
#pragma unroll
        for (int nt = 0; nt < 8; nt++)
#pragma unroll
            for (int j = 0; j < 4; j++) acc[mt][nt][j] = 0.f;

    const float* Abase = A + (size_t)bm * DD;
    const __half* Wbase = W + (size_t)bn * DD;

    const int aj = tid & 7;
    float4 areg[8];

    auto ldgA = [&](int kt) {
        const int k0 = kt * PBK;
#pragma unroll
        for (int i = 0; i < 8; i++) {
            const int r = (tid >> 3) + i * 16;
            areg[i] = *reinterpret_cast<const float4*>(Abase + (size_t)r * DD + k0 + aj * 4);
        }
    };
    auto stsA = [&](int buf) {
#pragma unroll
        for (int i = 0; i < 8; i++) {
            const int r = (tid >> 3) + i * 16;
            uint2 o;
            o.x = packh2(areg[i].x, areg[i].y);
            o.y = packh2(areg[i].z, areg[i].w);
            *reinterpret_cast<uint2*>(&As[buf * PASZH + r * PPDH + aj * 4]) = o;
        }
    };
    auto cpB = [&](int kt, int buf) {
        const int k0 = kt * PBK;
#pragma unroll
        for (int i = 0; i < 4; i++) {
            const int idx = tid + i * 128;
            const int r = idx >> 2, j = idx & 3;
            cp16(&Bs[buf * PASZH + r * PPDH + j * 8], Wbase + (size_t)r * DD + k0 + j * 8);
        }
        asm volatile("cp.async.commit_group;\n");
    };

    ldgA(0);
    stsA(0);
    cpB(0, 0);
    ldgA(1);

    for (int kt = 0; kt < PNKT; kt++) {
        const int buf = kt & 1;
        asm volatile("cp.async.wait_group 0;\n");
        __syncthreads();

        if (kt + 1 < PNKT) {
            cpB(kt + 1, buf ^ 1);
            stsA(buf ^ 1);
            if (kt + 2 < PNKT) ldgA(kt + 2);
        }

        const uint32_t Abu = (uint32_t)__cvta_generic_to_shared(&As[buf * PASZH]);
        const uint32_t Bbu = (uint32_t)__cvta_generic_to_shared(&Bs[buf * PASZH]);

#pragma unroll
        for (int ks = 0; ks < 2; ks++) {
            const int c = ks * 16;
            uint32_t af[4][4], bfq[4][4];
            {
                const int row_off = (sub & 1) * 8 + l7;
                const int col = c + (sub >> 1) * 8;
#pragma unroll
                for (int mt = 0; mt < 4; mt++) {
                    const int row = wm * 64 + mt * 16 + row_off;
                    ldsm4(Abu + (uint32_t)(row * PPDH + col) * 2, af[mt]);
                }
            }
            {
                const int row_off = (sub >> 1) * 8 + l7;
                const int col = c + (sub & 1) * 8;
#pragma unroll
                for (int ntp = 0; ntp < 4; ntp++) {
                    const int row = wn * 64 + ntp * 16 + row_off;
                    ldsm4(Bbu + (uint32_t)(row * PPDH + col) * 2, bfq[ntp]);
                }
            }
#pragma unroll
            for (int ntp = 0; ntp < 4; ntp++) {
                uint32_t b0[2] = {bfq[ntp][0], bfq[ntp][1]};
                uint32_t b1[2] = {bfq[ntp][2], bfq[ntp][3]};
#pragma unroll
                for (int mt = 0; mt < 4; mt++) {
                    mma16n8k16(acc[mt][2 * ntp],     af[mt], b0);
                    mma16n8k16(acc[mt][2 * ntp + 1], af[mt], b1);
                }
            }
        }
    }

#pragma unroll
    for (int mt = 0; mt < 4; mt++) {
        const int gm = bm + wm * 64 + mt * 16 + lq;
#pragma unroll
        for (int nt = 0; nt < 8; nt++) {
            const int gn = bn + wn * 64 + nt * 8 + (lr << 1);
            const int h = gn >> 6, dh = gn & 63;
            const int b0 = gm >> 11, t0 = gm & (TT - 1);
            *reinterpret_cast<uint32_t*>(
                &out[(((size_t)b0 * HH + h) * TT + t0) * DHH + dh]) =
                packh2(acc[mt][nt][0], acc[mt][nt][1]);
            const int gm1 = gm + 8;
            const int b1 = gm1 >> 11, t1 = gm1 & (TT - 1);
            *reinterpret_cast<uint32_t*>(
                &out[(((size_t)b1 * HH + h) * TT + t1) * DHH + dh]) =
                packh2(acc[mt][nt][2], acc[mt][nt][3]);
        }
    }
}

// ---------------------------------------------------------------------------
// O-projection: fp16 A (g_O) via cp.async, fp16 B (Wo), fp32 row-major out.
// ---------------------------------------------------------------------------
__global__ void __launch_bounds__(128, 2)
proj_o_kernel(float* __restrict__ out)
{
    extern __shared__ __half smh[];
    __half* As = smh;
    __half* Bs = smh + 2 * PASZH;

    const __half* A = g_O;
    const __half* W = g_RW + 3 * (size_t)(DD * DD);

    const int tid  = threadIdx.x;
    const int lane = tid & 31, warp = tid >> 5;
    const int wm = warp >> 1, wn = warp & 1;
    const int bm = blockIdx.y * PBM, bn = blockIdx.x * PBN;
    const int lq = lane >> 2, lr = lane & 3;
    const int sub = lane >> 3, l7 = lane & 7;

    float acc[4][8][4];
#pragma unroll
    for (int mt = 0; mt < 4; mt++)
#pragma unroll
        for (int nt = 0; nt < 8; nt++)
#pragma unroll
            for (int j = 0; j < 4; j++) acc[mt][nt][j] = 0.f;

    const __half* Abase = A + (size_t)bm * DD;
    const __half* Wbase = W + (size_t)bn * DD;

    auto load_tile = [&](int kt, int buf) {
        const int k0 = kt * PBK;
#pragma unroll
        for (int i = 0; i < 4; i++) {
            const int idx = tid + i * 128;
            const int r = idx >> 2, j = idx & 3;
            cp16(&As[buf * PASZH + r * PPDH + j * 8], Abase + (size_t)r * DD + k0 + j * 8);
        }
#pragma unroll
        for (int i = 0; i < 4; i++) {
            const int idx = tid + i * 128;
            const int r = idx >> 2, j = idx & 3;
            cp16(&Bs[buf * PASZH + r * PPDH + j * 8], Wbase + (size_t)r * DD + k0 + j * 8);
        }
        asm volatile("cp.async.commit_group;\n");
    };

    load_tile(0, 0);

    for (int kt = 0; kt < PNKT; kt++) {
        const int buf = kt & 1;
        if (kt + 1 < PNKT) {
            load_tile(kt + 1, buf ^ 1);
            asm volatile("cp.async.wait_group 1;\n");
        } else {
            asm volatile("cp.async.wait_group 0;\n");
        }
        __syncthreads();

        const uint32_t Abu = (uint32_t)__cvta_generic_to_shared(&As[buf * PASZH]);
        const uint32_t Bbu = (uint32_t)__cvta_generic_to_shared(&Bs[buf * PASZH]);

#pragma unroll
        for (int ks = 0; ks < 2; ks++) {
            const int c = ks * 16;
            uint32_t af[4][4], bfq[4][4];
            {
                const int row_off = (sub & 1) * 8 + l7;
                const int col = c + (sub >> 1) * 8;
#pragma unroll
                for (int mt = 0; mt < 4; mt++) {
                    const int row = wm * 64 + mt * 16 + row_off;
                    ldsm4(Abu + (uint32_t)(row * PPDH + col) * 2, af[mt]);
                }
            }
            {
                const int row_off = (sub >> 1) * 8 + l7;
                const int col = c + (sub & 1) * 8;
#pragma unroll
                for (int ntp = 0; ntp < 4; ntp++) {
                    const int row = wn * 64 + ntp * 16 + row_off;
                    ldsm4(Bbu + (uint32_t)(row * PPDH + col) * 2, bfq[ntp]);
                }
            }
#pragma unroll
            for (int ntp = 0; ntp < 4; ntp++) {
                uint32_t b0[2] = {bfq[ntp][0], bfq[ntp][1]};
                uint32_t b1[2] = {bfq[ntp][2], bfq[ntp][3]};
#pragma unroll
                for (int mt = 0; mt < 4; mt++) {
                    mma16n8k16(acc[mt][2 * ntp],     af[mt], b0);
                    mma16n8k16(acc[mt][2 * ntp + 1], af[mt], b1);
                }
            }
        }
        __syncthreads();
    }

#pragma unroll
    for (int mt = 0; mt < 4; mt++) {
        const int gm = bm + wm * 64 + mt * 16 + lq;
#pragma unroll
        for (int nt = 0; nt < 8; nt++) {
            const int gn = bn + wn * 64 + nt * 8 + (lr << 1);
            *reinterpret_cast<float2*>(&out[(size_t)gm * DD + gn]) =
                make_float2(acc[mt][nt][0], acc[mt][nt][1]);
            *reinterpret_cast<float2*>(&out[(size_t)(gm + 8) * DD + gn]) =
                make_float2(acc[mt][nt][2], acc[mt][nt][3]);
        }
    }
}

// ---------------------------------------------------------------------------
// FP16 flash attention: 64 q-rows/CTA, 4 CTAs/SM, f16x2 exp, ones-MMA row sums,
// LPT (heavy qi first).
// ---------------------------------------------------------------------------
#define AKPH 72
#define A_KS_OFF 0
#define A_VS_OFF 9216
#define A_PS_OFF 18432
#define A_SMEM   ((18432 + 4608) * 2)    // 46,080 B

__global__ void __launch_bounds__(128, 4) attn_kernel()
{
    extern __shared__ __half smh[];
    __half* Ps = smh + A_PS_OFF;

    const int qi = gridDim.x - 1 - blockIdx.x;   // LPT: heavy CTAs first
    const int h = blockIdx.y, b = blockIdx.z;
    const int tid = threadIdx.x, warp = tid >> 5, lane = tid & 31;
    const int len = g_len[b];
    const int lq = lane >> 2, lr = lane & 3;
    const int sub = lane >> 3, l7 = lane & 7;

    const size_t base = ((size_t)b * HH + h) * TT * DHH;
    const __half* __restrict__ Qb = g_Q + base;
    const __half* __restrict__ Kb = g_K + base;
    const __half* __restrict__ Vb = g_V + base;

    const uint32_t ps_u = (uint32_t)__cvta_generic_to_shared(Ps);

#pragma unroll
    for (int i = 0; i < 4; i++) {
        const int idx = tid + i * 128;
        const int r = idx >> 3, j = idx & 7;
        *reinterpret_cast<uint4*>(&Ps[r * AKPH + j * 8]) =
            *reinterpret_cast<const uint4*>(&Qb[(size_t)(qi * 64 + r) * DHH + j * 8]);
    }
    __syncthreads();

    uint32_t qf[4][4];
    {
        const int row = warp * 16 + (sub & 1) * 8 + l7;
        const int col_off = (sub >> 1) * 8;
#pragma unroll
        for (int ks = 0; ks < 4; ks++)
            ldsm4(ps_u + (uint32_t)(row * AKPH + ks * 16 + col_off) * 2, qf[ks]);
    }
    __syncthreads();

    float oacc[8][4];
#pragma unroll
    for (int nt = 0; nt < 8; nt++)
#pragma unroll
        for (int j = 0; j < 4; j++) oacc[nt][j] = 0.f;

    float lacc[4] = {0.f, 0.f, 0.f, 0.f};        // row-sum accumulator (ones-MMA)
    float mrowA = -1e30f, mrowB = -1e30f;

    const int ktend = min(qi + 1, (len + 63) >> 6);
    const float SE = ATT_SCALE * LOG2E_F;
    const uint32_t ones2[2] = {0x3C003C00u, 0x3C003C00u};

    auto load_kv = [&](int kt, int bufi) {
        const __half* Kp = Kb + (size_t)(kt * 64) * DHH;
        const __half* Vp = Vb + (size_t)(kt * 64) * DHH;
        __half* Kd = smh + A_KS_OFF + bufi * 64 * AKPH;
        __half* Vd = smh + A_VS_OFF + bufi * 64 * AKPH;
#pragma unroll
        for (int i = 0; i < 4; i++) {
            const int idx = tid + i * 128;
            const int r = idx >> 3, j = idx & 7;
            cp16(Kd + r * AKPH + j * 8, Kp + (size_t)r * DHH + j * 8);
            cp16(Vd + r * AKPH + j * 8, Vp + (size_t)r * DHH + j * 8);
        }
        asm volatile("cp.async.commit_group;\n");
    };

    load_kv(0, 0);

    const int prow = warp * 16 + lq;

    for (int kt = 0; kt < ktend; kt++) {
        const int buf = kt & 1;
        asm volatile("cp.async.wait_group 0;\n");
        __syncthreads();
        if (kt + 1 < ktend) load_kv(kt + 1, buf ^ 1);

        const uint32_t kt_u = (uint32_t)__cvta_generic_to_shared(smh + A_KS_OFF + buf * 64 * AKPH);
        const uint32_t vt_u = (uint32_t)__cvta_generic_to_shared(smh + A_VS_OFF + buf * 64 * AKPH);

        // ---- S = Q K^T ----
        float s[8][4];
#pragma unroll
        for (int nt = 0; nt < 8; nt++)
#pragma unroll
            for (int j = 0; j < 4; j++) s[nt][j] = 0.f;
        {
            const int row_off = (sub >> 1) * 8 + l7;
            const int col_off = (sub & 1) * 8;
#pragma unroll
            for (int ks = 0; ks < 4; ks++) {
                const int c = ks * 16 + col_off;
#pragma unroll
                for (int ntp = 0; ntp < 4; ntp++) {
                    uint32_t kf[4];
                    ldsm4(kt_u + (uint32_t)((ntp * 16 + row_off) * AKPH + c) * 2, kf);
                    uint32_t b0[2] = {kf[0], kf[1]};
                    uint32_t b1[2] = {kf[2], kf[3]};
                    mma16n8k16(s[2 * ntp],     qf[ks], b0);
                    mma16n8k16(s[2 * ntp + 1], qf[ks], b1);
                }
            }
        }

        // ---- scale + mask ----
        const bool need_mask = (kt == qi) || (((kt + 1) << 6) > len);
        if (need_mask) {
            const int qg0 = qi * 64 + warp * 16 + lq;
#pragma unroll
            for (int nt = 0; nt < 8; nt++) {
#pragma unroll
                for (int j = 0; j < 4; j++) {
                    float v = s[nt][j] * SE;
                    const int kg = kt * 64 + nt * 8 + (lr << 1) + (j & 1);
                    const int qg = qg0 + ((j & 2) << 2);
                    if (kg > qg || kg >= len) v = -1e30f;
                    s[nt][j] = v;
                }
            }
        } else {
#pragma unroll
            for (int nt = 0; nt < 8; nt++)
#pragma unroll
                for (int j = 0; j < 4; j++) s[nt][j] *= SE;
        }

        // ---- online softmax: max reduce, f16x2 exp, store P ----
        {
            float tA = -1e30f, tB = -1e30f;
#pragma unroll
            for (int nt = 0; nt < 8; nt++) {
                tA = fmaxf(tA, fmaxf(s[nt][0], s[nt][1]));
                tB = fmaxf(tB, fmaxf(s[nt][2], s[nt][3]));
            }
            tA = fmaxf(tA, __shfl_xor_sync(0xffffffffu, tA, 1));
            tA = fmaxf(tA, __shfl_xor_sync(0xffffffffu, tA, 2));
            tB = fmaxf(tB, __shfl_xor_sync(0xffffffffu, tB, 1));
            tB = fmaxf(tB, __shfl_xor_sync(0xffffffffu, tB, 2));
            const float mA = fmaxf(mrowA, tA), mB = fmaxf(mrowB, tB);
            const float aA = exp2_(mrowA - mA), aB = exp2_(mrowB - mB);

#pragma unroll
            for (int nt = 0; nt < 8; nt++) {
                const uint32_t x0 = packh2(s[nt][0] - mA, s[nt][1] - mA);
                const uint32_t x1 = packh2(s[nt][2] - mB, s[nt][3] - mB);
                const int c = nt * 8 + (lr << 1);
                *reinterpret_cast<uint32_t*>(&Ps[prow * AKPH + c]) = ex2h2(x0);
                *reinterpret_cast<uint32_t*>(&Ps[(prow + 8) * AKPH + c]) = ex2h2(x1);
            }
            mrowA = mA;
            mrowB = mB;
            lacc[0] *= aA; lacc[1] *= aA;
            lacc[2] *= aB; lacc[3] *= aB;
#pragma unroll
            for (int nt = 0; nt < 8; nt++) {
                oacc[nt][0] *= aA; oacc[nt][1] *= aA;
                oacc[nt][2] *= aB; oacc[nt][3] *= aB;
            }
        }
        __syncwarp();

        // ---- O += P V ; l += P @ ones ----
        {
            const int prow_off = warp * 16 + (sub & 1) * 8 + l7;
            const int pcol_off = (sub >> 1) * 8;
#pragma unroll
            for (int ks = 0; ks < 4; ks++) {
                uint32_t pa[4];
                ldsm4(ps_u + (uint32_t)(prow_off * AKPH + ks * 16 + pcol_off) * 2, pa);
                mma16n8k16(lacc, pa, ones2);
#pragma unroll
                for (int ntp = 0; ntp < 4; ntp++) {
                    const int row = ks * 16 + ((lane >> 3) & 1) * 8 + (lane & 7);
                    const int col = ntp * 16 + ((lane >> 4) << 3);
                    uint32_t vf[4];
                    ldsm4t(vt_u + (uint32_t)(row * AKPH + col) * 2, vf);
                    uint32_t b0[2] = {vf[0], vf[1]}, b1[2] = {vf[2], vf[3]};
                    mma16n8k16(oacc[2 * ntp],     pa, b0);
                    mma16n8k16(oacc[2 * ntp + 1], pa, b1);
                }
            }
        }
        __syncwarp();
    }

    // ---- finalize: fp16 O in [b,t,h*64+dh] ----
    __half* __restrict__ Ob = g_O + ((size_t)b * TT) * DD + h * DHH;
    {
        const float invA = 1.f / lacc[0], invB = 1.f / lacc[2];
        const int q0 = qi * 64 + warp * 16 + lq;
#pragma unroll
        for (int nt = 0; nt < 8; nt++) {
            const int dh = nt * 8 + (lr << 1);
            *reinterpret_cast<uint32_t*>(&Ob[(size_t)q0 * DD + dh]) =
                packh2(oacc[nt][0] * invA, oacc[nt][1] * invA);
            *reinterpret_cast<uint32_t*>(&Ob[(size_t)(q0 + 8) * DD + dh]) =
                packh2(oacc[nt][2] * invB, oacc[nt][3] * invB);
        }
    }
}

// ---------------------------------------------------------------------------
// Launch
// ---------------------------------------------------------------------------
extern "C" void kernel_launch(void* const* d_in, const int* in_sizes, int n_in,
                              void* d_out, int out_size)
{
    const float* big[4] = {nullptr, nullptr, nullptr, nullptr};
    const float* w[4]   = {nullptr, nullptr, nullptr, nullptr};
    const unsigned char* kpm = nullptr;
    int nbig = 0, nw = 0;
    for (int i = 0; i < n_in; i++) {
        if (in_sizes[i] == TT * TT && nbig < 4) big[nbig++] = (const float*)d_in[i];
        else if (in_sizes[i] == DD * DD && nw < 4) w[nw++] = (const float*)d_in[i];
        else if (in_sizes[i] == BB * TT) kpm = (const unsigned char*)d_in[i];
    }
    const float* query = big[0];
    const float* key_t = big[1];
    const float* value = big[2];
    const float* Wq = w[0];
    const float* Wk = w[1];
    const float* Wv = w[2];
    const float* Wo = w[3];
    float* out = (float*)d_out;

    static bool attr_set = false;
    if (!attr_set) {
        cudaFuncSetAttribute(proj_qkv_kernel, cudaFuncAttributeMaxDynamicSharedMemorySize, PSMEM);
        cudaFuncSetAttribute(proj_o_kernel, cudaFuncAttributeMaxDynamicSharedMemorySize, PSMEM);
        cudaFuncSetAttribute(attn_kernel, cudaFuncAttributeMaxDynamicSharedMemorySize, A_SMEM);
        attr_set = true;
    }

    lens_kernel<<<BB, 256>>>(kpm);
    round_kernel<<<dim3((DD * DD) / 4 / 256, 4), 256>>>(Wq, Wk, Wv, Wo);
    proj_qkv_kernel<<<dim3(DD / PBN, MM / PBM, 3), 128, PSMEM>>>(query, key_t, value);
    attn_kernel<<<dim3(TT / 64, HH, BB), 128, A_SMEM>>>();
    proj_o_kernel<<<dim3(DD / PBN, MM / PBM, 1), 128, PSMEM>>>(out);
}